// round 1
// baseline (speedup 1.0000x reference)
#include <cuda_runtime.h>
#include <math.h>

#define NN 50000
#define NE 800000
#define INF 128
#define HIDF 256
#define OUTF 128
#define KE1 257   // 2*IN + 1
#define KN1 384   // IN + HID
#define TBK 16

__device__ __forceinline__ float silu_f(float x) {
    return x * (1.0f / (1.0f + __expf(-x)));
}

// ---------------- scratch (device globals; no allocation allowed) ----------------
__device__ float g_xdiff[NE * 4];                       // nx,ny,nz,radial
__device__ float g_h1[(size_t)NE * HIDF];               // 819 MB
__device__ float g_msgh[(size_t)NE * HIDF];             // 819 MB
__device__ float g_hneigh[(size_t)NN * HIDF];           // segment-sum of msg_h
__device__ float g_xsum[NN * 3];
__device__ float g_deg[NN];
__device__ float g_hn1[(size_t)NN * HIDF];
__device__ float g_colsum[OUTF];
__device__ float g_colsq[OUTF];

// ---------------- edge geometry ----------------
__global__ void k_geom(const float* __restrict__ coord,
                       const int* __restrict__ src,
                       const int* __restrict__ dst) {
    int e = blockIdx.x * blockDim.x + threadIdx.x;
    if (e >= NE) return;
    int s = src[e], d = dst[e];
    float ax = coord[s * 3 + 0], ay = coord[s * 3 + 1], az = coord[s * 3 + 2];
    float bx = coord[d * 3 + 0], by = coord[d * 3 + 1], bz = coord[d * 3 + 2];
    float dx = ax - bx, dy = ay - by, dz = az - bz;
    float r = dx * dx + dy * dy + dz * dz;
    float inv = 1.0f / (sqrtf(r) + 1e-30f);
    ((float4*)g_xdiff)[e] = make_float4(dx * inv, dy * inv, dz * inv, r);
    atomicAdd(&g_deg[d], 1.0f);
}

// ---------------- GEMM 1: h1 = silu([nf[src], nf[dst], radial] @ W_e1 + b) ----------------
__global__ __launch_bounds__(256, 2)
void k_e1(const float* __restrict__ nf, const int* __restrict__ src,
          const int* __restrict__ dst, const float* __restrict__ W,
          const float* __restrict__ b) {
    __shared__ float As[TBK][128 + 4];
    __shared__ float Bs[TBK][128 + 4];
    __shared__ int s_src[128];
    __shared__ int s_dst[128];
    __shared__ float s_rad[128];
    const int tid = threadIdx.x;
    const int row0 = blockIdx.x * 128;
    const int col0 = blockIdx.y * 128;
    if (tid < 128) {
        int e = row0 + tid;
        s_src[tid] = src[e];
        s_dst[tid] = dst[e];
        s_rad[tid] = g_xdiff[e * 4 + 3];
    }
    __syncthreads();
    const int tx = tid & 15;
    const int ty = tid >> 4;
    float acc[8][8];
#pragma unroll
    for (int i = 0; i < 8; i++)
#pragma unroll
        for (int j = 0; j < 8; j++) acc[i][j] = 0.0f;

    const int nkt = (KE1 + TBK - 1) / TBK;  // 17
    for (int kt = 0; kt < nkt; kt++) {
        // A tile (gathered): 128 x 16
#pragma unroll
        for (int i = 0; i < 2; i++) {
            int f = tid + i * 256;
            int r = f >> 2;
            int kk = (f & 3) << 2;
            int kg = kt * TBK + kk;
            float4 v = make_float4(0.f, 0.f, 0.f, 0.f);
            if (kg + 3 < 2 * INF) {
                const float* p = (kg < INF) ? (nf + s_src[r] * INF + kg)
                                            : (nf + s_dst[r] * INF + (kg - INF));
                v = *(const float4*)p;
            } else if (kg == 2 * INF) {
                v.x = s_rad[r];
            }
            As[kk + 0][r] = v.x; As[kk + 1][r] = v.y;
            As[kk + 2][r] = v.z; As[kk + 3][r] = v.w;
        }
        // B tile: 16 x 128 of W (ld = 256)
#pragma unroll
        for (int i = 0; i < 2; i++) {
            int f = tid + i * 256;
            int kk = f >> 5;
            int c = (f & 31) << 2;
            int kg = kt * TBK + kk;
            float4 v = make_float4(0.f, 0.f, 0.f, 0.f);
            if (kg < KE1) v = *(const float4*)(W + (size_t)kg * HIDF + col0 + c);
            *(float4*)&Bs[kk][c] = v;
        }
        __syncthreads();
#pragma unroll
        for (int k = 0; k < TBK; k++) {
            float4 a0 = *(float4*)&As[k][ty * 8];
            float4 a1 = *(float4*)&As[k][ty * 8 + 4];
            float4 b0 = *(float4*)&Bs[k][tx * 8];
            float4 b1 = *(float4*)&Bs[k][tx * 8 + 4];
            float ar[8] = {a0.x, a0.y, a0.z, a0.w, a1.x, a1.y, a1.z, a1.w};
            float br[8] = {b0.x, b0.y, b0.z, b0.w, b1.x, b1.y, b1.z, b1.w};
#pragma unroll
            for (int i = 0; i < 8; i++)
#pragma unroll
                for (int j = 0; j < 8; j++) acc[i][j] += ar[i] * br[j];
        }
        __syncthreads();
    }
    float bb[8];
#pragma unroll
    for (int j = 0; j < 8; j++) bb[j] = b[col0 + tx * 8 + j];
#pragma unroll
    for (int i = 0; i < 8; i++) {
        int e = row0 + ty * 8 + i;
        float4 o0, o1;
        o0.x = silu_f(acc[i][0] + bb[0]); o0.y = silu_f(acc[i][1] + bb[1]);
        o0.z = silu_f(acc[i][2] + bb[2]); o0.w = silu_f(acc[i][3] + bb[3]);
        o1.x = silu_f(acc[i][4] + bb[4]); o1.y = silu_f(acc[i][5] + bb[5]);
        o1.z = silu_f(acc[i][6] + bb[6]); o1.w = silu_f(acc[i][7] + bb[7]);
        *(float4*)(g_h1 + (size_t)e * HIDF + col0 + tx * 8) = o0;
        *(float4*)(g_h1 + (size_t)e * HIDF + col0 + tx * 8 + 4) = o1;
    }
}

// ---------------- GEMM 2: msg_h = silu(h1 @ W_e2 + b); aggregate into h_neigh[dst] ----------------
__global__ __launch_bounds__(256, 2)
void k_e2(const int* __restrict__ dst, const float* __restrict__ W,
          const float* __restrict__ b) {
    __shared__ float As[TBK][128 + 4];
    __shared__ float Bs[TBK][128 + 4];
    __shared__ int s_dst[128];
    const int tid = threadIdx.x;
    const int row0 = blockIdx.x * 128;
    const int col0 = blockIdx.y * 128;
    if (tid < 128) s_dst[tid] = dst[row0 + tid];
    __syncthreads();
    const int tx = tid & 15;
    const int ty = tid >> 4;
    float acc[8][8];
#pragma unroll
    for (int i = 0; i < 8; i++)
#pragma unroll
        for (int j = 0; j < 8; j++) acc[i][j] = 0.0f;

    for (int kt = 0; kt < HIDF / TBK; kt++) {
#pragma unroll
        for (int i = 0; i < 2; i++) {
            int f = tid + i * 256;
            int r = f >> 2;
            int kk = (f & 3) << 2;
            float4 v = *(const float4*)(g_h1 + (size_t)(row0 + r) * HIDF + kt * TBK + kk);
            As[kk + 0][r] = v.x; As[kk + 1][r] = v.y;
            As[kk + 2][r] = v.z; As[kk + 3][r] = v.w;
        }
#pragma unroll
        for (int i = 0; i < 2; i++) {
            int f = tid + i * 256;
            int kk = f >> 5;
            int c = (f & 31) << 2;
            *(float4*)&Bs[kk][c] =
                *(const float4*)(W + (size_t)(kt * TBK + kk) * HIDF + col0 + c);
        }
        __syncthreads();
#pragma unroll
        for (int k = 0; k < TBK; k++) {
            float4 a0 = *(float4*)&As[k][ty * 8];
            float4 a1 = *(float4*)&As[k][ty * 8 + 4];
            float4 b0 = *(float4*)&Bs[k][tx * 8];
            float4 b1 = *(float4*)&Bs[k][tx * 8 + 4];
            float ar[8] = {a0.x, a0.y, a0.z, a0.w, a1.x, a1.y, a1.z, a1.w};
            float br[8] = {b0.x, b0.y, b0.z, b0.w, b1.x, b1.y, b1.z, b1.w};
#pragma unroll
            for (int i = 0; i < 8; i++)
#pragma unroll
                for (int j = 0; j < 8; j++) acc[i][j] += ar[i] * br[j];
        }
        __syncthreads();
    }
    float bb[8];
#pragma unroll
    for (int j = 0; j < 8; j++) bb[j] = b[col0 + tx * 8 + j];
#pragma unroll
    for (int i = 0; i < 8; i++) {
        int e = row0 + ty * 8 + i;
        int d = s_dst[ty * 8 + i];
        float v[8];
#pragma unroll
        for (int j = 0; j < 8; j++) v[j] = silu_f(acc[i][j] + bb[j]);
        float4 o0 = make_float4(v[0], v[1], v[2], v[3]);
        float4 o1 = make_float4(v[4], v[5], v[6], v[7]);
        *(float4*)(g_msgh + (size_t)e * HIDF + col0 + tx * 8) = o0;
        *(float4*)(g_msgh + (size_t)e * HIDF + col0 + tx * 8 + 4) = o1;
        float* hn = g_hneigh + (size_t)d * HIDF + col0 + tx * 8;
#pragma unroll
        for (int j = 0; j < 8; j++) atomicAdd(hn + j, v[j]);
    }
}

// ---------------- coord GEMM: s = silu(msg_h @ W_c1 + b) . W_c2 ; x_sum[dst] += s * xdiff ----------------
__global__ __launch_bounds__(256, 2)
void k_c(const int* __restrict__ dst, const float* __restrict__ W,
         const float* __restrict__ b, const float* __restrict__ Wc2) {
    __shared__ float As[TBK][64 + 4];
    __shared__ float Bs[TBK][256];
    __shared__ float s_w2[256];
    __shared__ float red[64];
    __shared__ int s_dst[64];
    const int tid = threadIdx.x;
    const int row0 = blockIdx.x * 64;
    s_w2[tid] = Wc2[tid];
    if (tid < 64) s_dst[tid] = dst[row0 + tid];
    __syncthreads();
    const int tx = tid & 31;
    const int ty = tid >> 5;
    float acc[8][8];
#pragma unroll
    for (int i = 0; i < 8; i++)
#pragma unroll
        for (int j = 0; j < 8; j++) acc[i][j] = 0.0f;

    for (int kt = 0; kt < HIDF / TBK; kt++) {
        {
            int f = tid;
            int r = f >> 2;
            int kk = (f & 3) << 2;
            float4 v = *(const float4*)(g_msgh + (size_t)(row0 + r) * HIDF + kt * TBK + kk);
            As[kk + 0][r] = v.x; As[kk + 1][r] = v.y;
            As[kk + 2][r] = v.z; As[kk + 3][r] = v.w;
        }
#pragma unroll
        for (int i = 0; i < 4; i++) {
            int f = tid + i * 256;
            int kk = f >> 6;
            int c = (f & 63) << 2;
            *(float4*)&Bs[kk][c] =
                *(const float4*)(W + (size_t)(kt * TBK + kk) * HIDF + c);
        }
        __syncthreads();
#pragma unroll
        for (int k = 0; k < TBK; k++) {
            float4 a0 = *(float4*)&As[k][ty * 8];
            float4 a1 = *(float4*)&As[k][ty * 8 + 4];
            float4 b0 = *(float4*)&Bs[k][tx * 8];
            float4 b1 = *(float4*)&Bs[k][tx * 8 + 4];
            float ar[8] = {a0.x, a0.y, a0.z, a0.w, a1.x, a1.y, a1.z, a1.w};
            float br[8] = {b0.x, b0.y, b0.z, b0.w, b1.x, b1.y, b1.z, b1.w};
#pragma unroll
            for (int i = 0; i < 8; i++)
#pragma unroll
                for (int j = 0; j < 8; j++) acc[i][j] += ar[i] * br[j];
        }
        __syncthreads();
    }
#pragma unroll
    for (int i = 0; i < 8; i++) {
        float s = 0.0f;
#pragma unroll
        for (int j = 0; j < 8; j++) {
            int c = tx * 8 + j;
            s += silu_f(acc[i][j] + b[c]) * s_w2[c];
        }
#pragma unroll
        for (int off = 16; off; off >>= 1) s += __shfl_xor_sync(0xffffffffu, s, off);
        if (tx == 0) red[ty * 8 + i] = s;
    }
    __syncthreads();
    if (tid < 64) {
        int e = row0 + tid;
        float s = red[tid];
        float4 xd = *(const float4*)(g_xdiff + (size_t)e * 4);
        int d = s_dst[tid];
        atomicAdd(&g_xsum[d * 3 + 0], s * xd.x);
        atomicAdd(&g_xsum[d * 3 + 1], s * xd.y);
        atomicAdd(&g_xsum[d * 3 + 2], s * xd.z);
    }
}

// ---------------- node GEMM 1: hn1 = silu([nf, h_neigh] @ W_n1 + b) ----------------
__global__ __launch_bounds__(256, 2)
void k_n1(const float* __restrict__ nf, const float* __restrict__ W,
          const float* __restrict__ b) {
    __shared__ float As[TBK][128 + 4];
    __shared__ float Bs[TBK][128 + 4];
    const int tid = threadIdx.x;
    const int row0 = blockIdx.x * 128;
    const int col0 = blockIdx.y * 128;
    const int tx = tid & 15;
    const int ty = tid >> 4;
    float acc[8][8];
#pragma unroll
    for (int i = 0; i < 8; i++)
#pragma unroll
        for (int j = 0; j < 8; j++) acc[i][j] = 0.0f;

    for (int kt = 0; kt < KN1 / TBK; kt++) {  // 24
#pragma unroll
        for (int i = 0; i < 2; i++) {
            int f = tid + i * 256;
            int r = f >> 2;
            int kk = (f & 3) << 2;
            int kg = kt * TBK + kk;
            int rr = min(row0 + r, NN - 1);
            float4 v;
            if (kg < INF)
                v = *(const float4*)(nf + (size_t)rr * INF + kg);
            else
                v = *(const float4*)(g_hneigh + (size_t)rr * HIDF + (kg - INF));
            As[kk + 0][r] = v.x; As[kk + 1][r] = v.y;
            As[kk + 2][r] = v.z; As[kk + 3][r] = v.w;
        }
#pragma unroll
        for (int i = 0; i < 2; i++) {
            int f = tid + i * 256;
            int kk = f >> 5;
            int c = (f & 31) << 2;
            *(float4*)&Bs[kk][c] =
                *(const float4*)(W + (size_t)(kt * TBK + kk) * HIDF + col0 + c);
        }
        __syncthreads();
#pragma unroll
        for (int k = 0; k < TBK; k++) {
            float4 a0 = *(float4*)&As[k][ty * 8];
            float4 a1 = *(float4*)&As[k][ty * 8 + 4];
            float4 b0 = *(float4*)&Bs[k][tx * 8];
            float4 b1 = *(float4*)&Bs[k][tx * 8 + 4];
            float ar[8] = {a0.x, a0.y, a0.z, a0.w, a1.x, a1.y, a1.z, a1.w};
            float br[8] = {b0.x, b0.y, b0.z, b0.w, b1.x, b1.y, b1.z, b1.w};
#pragma unroll
            for (int i = 0; i < 8; i++)
#pragma unroll
                for (int j = 0; j < 8; j++) acc[i][j] += ar[i] * br[j];
        }
        __syncthreads();
    }
    float bb[8];
#pragma unroll
    for (int j = 0; j < 8; j++) bb[j] = b[col0 + tx * 8 + j];
#pragma unroll
    for (int i = 0; i < 8; i++) {
        int row = row0 + ty * 8 + i;
        if (row < NN) {
            float4 o0, o1;
            o0.x = silu_f(acc[i][0] + bb[0]); o0.y = silu_f(acc[i][1] + bb[1]);
            o0.z = silu_f(acc[i][2] + bb[2]); o0.w = silu_f(acc[i][3] + bb[3]);
            o1.x = silu_f(acc[i][4] + bb[4]); o1.y = silu_f(acc[i][5] + bb[5]);
            o1.z = silu_f(acc[i][6] + bb[6]); o1.w = silu_f(acc[i][7] + bb[7]);
            *(float4*)(g_hn1 + (size_t)row * HIDF + col0 + tx * 8) = o0;
            *(float4*)(g_hn1 + (size_t)row * HIDF + col0 + tx * 8 + 4) = o1;
        }
    }
}

// ---------------- node GEMM 2: h = hn1 @ W_n2 + b ; write pre-BN h and column stats ----------------
__global__ __launch_bounds__(256, 2)
void k_n2(const float* __restrict__ W, const float* __restrict__ b,
          float* __restrict__ out) {
    __shared__ float As[TBK][128 + 4];
    __shared__ float Bs[TBK][128 + 4];
    __shared__ float csum[128];
    __shared__ float csq[128];
    const int tid = threadIdx.x;
    const int row0 = blockIdx.x * 128;
    if (tid < 128) { csum[tid] = 0.0f; csq[tid] = 0.0f; }
    const int tx = tid & 15;
    const int ty = tid >> 4;
    float acc[8][8];
#pragma unroll
    for (int i = 0; i < 8; i++)
#pragma unroll
        for (int j = 0; j < 8; j++) acc[i][j] = 0.0f;

    for (int kt = 0; kt < HIDF / TBK; kt++) {
#pragma unroll
        for (int i = 0; i < 2; i++) {
            int f = tid + i * 256;
            int r = f >> 2;
            int kk = (f & 3) << 2;
            int rr = min(row0 + r, NN - 1);
            float4 v = *(const float4*)(g_hn1 + (size_t)rr * HIDF + kt * TBK + kk);
            As[kk + 0][r] = v.x; As[kk + 1][r] = v.y;
            As[kk + 2][r] = v.z; As[kk + 3][r] = v.w;
        }
#pragma unroll
        for (int i = 0; i < 2; i++) {
            int f = tid + i * 256;
            int kk = f >> 5;
            int c = (f & 31) << 2;
            *(float4*)&Bs[kk][c] =
                *(const float4*)(W + (size_t)(kt * TBK + kk) * OUTF + c);
        }
        __syncthreads();
#pragma unroll
        for (int k = 0; k < TBK; k++) {
            float4 a0 = *(float4*)&As[k][ty * 8];
            float4 a1 = *(float4*)&As[k][ty * 8 + 4];
            float4 b0 = *(float4*)&Bs[k][tx * 8];
            float4 b1 = *(float4*)&Bs[k][tx * 8 + 4];
            float ar[8] = {a0.x, a0.y, a0.z, a0.w, a1.x, a1.y, a1.z, a1.w};
            float br[8] = {b0.x, b0.y, b0.z, b0.w, b1.x, b1.y, b1.z, b1.w};
#pragma unroll
            for (int i = 0; i < 8; i++)
#pragma unroll
                for (int j = 0; j < 8; j++) acc[i][j] += ar[i] * br[j];
        }
        __syncthreads();
    }
    float bb[8];
#pragma unroll
    for (int j = 0; j < 8; j++) bb[j] = b[tx * 8 + j];
    float cs[8], cq[8];
#pragma unroll
    for (int j = 0; j < 8; j++) { cs[j] = 0.0f; cq[j] = 0.0f; }
#pragma unroll
    for (int i = 0; i < 8; i++) {
        int row = row0 + ty * 8 + i;
        if (row < NN) {
            float h[8];
#pragma unroll
            for (int j = 0; j < 8; j++) {
                h[j] = acc[i][j] + bb[j];
                cs[j] += h[j];
                cq[j] += h[j] * h[j];
            }
            *(float4*)(out + (size_t)row * OUTF + tx * 8) =
                make_float4(h[0], h[1], h[2], h[3]);
            *(float4*)(out + (size_t)row * OUTF + tx * 8 + 4) =
                make_float4(h[4], h[5], h[6], h[7]);
        }
    }
#pragma unroll
    for (int j = 0; j < 8; j++) {
        atomicAdd(&csum[tx * 8 + j], cs[j]);
        atomicAdd(&csq[tx * 8 + j], cq[j]);
    }
    __syncthreads();
    if (tid < 128) {
        atomicAdd(&g_colsum[tid], csum[tid]);
        atomicAdd(&g_colsq[tid], csq[tid]);
    }
}

// ---------------- x output: x = coord + x_sum / max(deg,1) ----------------
__global__ void k_xout(const float* __restrict__ coord, float* __restrict__ out) {
    int n = blockIdx.x * blockDim.x + threadIdx.x;
    if (n >= NN) return;
    float inv = 1.0f / fmaxf(g_deg[n], 1.0f);
    float* o = out + (size_t)NN * OUTF + n * 3;
    o[0] = coord[n * 3 + 0] + g_xsum[n * 3 + 0] * inv;
    o[1] = coord[n * 3 + 1] + g_xsum[n * 3 + 1] * inv;
    o[2] = coord[n * 3 + 2] + g_xsum[n * 3 + 2] * inv;
}

// ---------------- BatchNorm finalize ----------------
__global__ void k_bn(const float* __restrict__ gamma, const float* __restrict__ beta,
                     float* __restrict__ out) {
    int idx = blockIdx.x * blockDim.x + threadIdx.x;
    if (idx >= NN * OUTF) return;
    int c = idx & (OUTF - 1);
    const float invN = 1.0f / (float)NN;
    float mu = g_colsum[c] * invN;
    float var = g_colsq[c] * invN - mu * mu;
    float h = out[idx];
    out[idx] = (h - mu) * rsqrtf(var + 1e-5f) * gamma[c] + beta[c];
}

// ---------------- launch ----------------
extern "C" void kernel_launch(void* const* d_in, const int* in_sizes, int n_in,
                              void* d_out, int out_size) {
    const float* nf    = (const float*)d_in[0];
    const float* coord = (const float*)d_in[1];
    const int*   src   = (const int*)d_in[2];
    const int*   dst   = (const int*)d_in[3];
    const float* We1   = (const float*)d_in[4];
    const float* be1   = (const float*)d_in[5];
    const float* We2   = (const float*)d_in[6];
    const float* be2   = (const float*)d_in[7];
    const float* Wc1   = (const float*)d_in[8];
    const float* bc1   = (const float*)d_in[9];
    const float* Wc2   = (const float*)d_in[10];
    const float* Wn1   = (const float*)d_in[11];
    const float* bn1   = (const float*)d_in[12];
    const float* Wn2   = (const float*)d_in[13];
    const float* bn2   = (const float*)d_in[14];
    const float* gamma = (const float*)d_in[15];
    const float* beta  = (const float*)d_in[16];
    float* out = (float*)d_out;

    void* p;
    cudaGetSymbolAddress(&p, g_hneigh);
    cudaMemsetAsync(p, 0, sizeof(float) * (size_t)NN * HIDF);
    cudaGetSymbolAddress(&p, g_xsum);
    cudaMemsetAsync(p, 0, sizeof(float) * NN * 3);
    cudaGetSymbolAddress(&p, g_deg);
    cudaMemsetAsync(p, 0, sizeof(float) * NN);
    cudaGetSymbolAddress(&p, g_colsum);
    cudaMemsetAsync(p, 0, sizeof(float) * OUTF);
    cudaGetSymbolAddress(&p, g_colsq);
    cudaMemsetAsync(p, 0, sizeof(float) * OUTF);

    k_geom<<<(NE + 255) / 256, 256>>>(coord, src, dst);

    dim3 ge(NE / 128, HIDF / 128);  // (6250, 2)
    k_e1<<<ge, 256>>>(nf, src, dst, We1, be1);
    k_e2<<<ge, 256>>>(dst, We2, be2);
    k_c<<<NE / 64, 256>>>(dst, Wc1, bc1, Wc2);

    dim3 gn((NN + 127) / 128, HIDF / 128);  // (391, 2)
    k_n1<<<gn, 256>>>(nf, Wn1, bn1);
    k_n2<<<(NN + 127) / 128, 256>>>(Wn2, bn2, out);

    k_xout<<<(NN + 255) / 256, 256>>>(coord, out);
    k_bn<<<(NN * OUTF + 255) / 256, 256>>>(gamma, beta, out);
}

// round 2
// speedup vs baseline: 1.1045x; 1.1045x over previous
#include <cuda_runtime.h>
#include <math.h>

#define NN 50000
#define NE 800000
#define INF 128
#define HIDF 256
#define OUTF 128
#define KE1 257   // 2*IN + 1
#define KN1 384   // IN + HID
#define TBK 16

typedef unsigned long long u64;

__device__ __forceinline__ float silu_f(float x) {
    return x * (1.0f / (1.0f + __expf(-x)));
}

// ---- packed f32x2 helpers (sm_100+) ----
__device__ __forceinline__ u64 pk2(float lo, float hi) {
    u64 r;
    asm("mov.b64 %0, {%1, %2};" : "=l"(r) : "f"(lo), "f"(hi));
    return r;
}
__device__ __forceinline__ u64 pkb(float x) {  // broadcast
    u64 r;
    asm("mov.b64 %0, {%1, %1};" : "=l"(r) : "f"(x));
    return r;
}
__device__ __forceinline__ void upk2(u64 v, float& lo, float& hi) {
    asm("mov.b64 {%0, %1}, %2;" : "=f"(lo), "=f"(hi) : "l"(v));
}
__device__ __forceinline__ void fma2(u64& acc, u64 a, u64 b) {
    asm("fma.rn.f32x2 %0, %1, %2, %0;" : "+l"(acc) : "l"(a), "l"(b));
}

// 8x8 microtile FMA step with packed math: acc2[8][4] += ar[i] * br2[j]
__device__ __forceinline__ void mt_step(u64 (&acc2)[8][4], const float* __restrict__ Arow,
                                        const float* __restrict__ Brow, int ty8, int tx8) {
    float4 a0 = *(const float4*)(Arow + ty8);
    float4 a1 = *(const float4*)(Arow + ty8 + 4);
    float4 b0 = *(const float4*)(Brow + tx8);
    float4 b1 = *(const float4*)(Brow + tx8 + 4);
    float ar[8] = {a0.x, a0.y, a0.z, a0.w, a1.x, a1.y, a1.z, a1.w};
    u64 br2[4] = {pk2(b0.x, b0.y), pk2(b0.z, b0.w), pk2(b1.x, b1.y), pk2(b1.z, b1.w)};
#pragma unroll
    for (int i = 0; i < 8; i++) {
        u64 aa = pkb(ar[i]);
#pragma unroll
        for (int jp = 0; jp < 4; jp++) fma2(acc2[i][jp], aa, br2[jp]);
    }
}

__device__ __forceinline__ void red_v4(float* p, float a, float b, float c, float d) {
    asm volatile("red.global.add.v4.f32 [%0], {%1, %2, %3, %4};"
                 :: "l"(p), "f"(a), "f"(b), "f"(c), "f"(d) : "memory");
}

// ---------------- scratch (device globals; no allocation allowed) ----------------
__device__ float g_xdiff[NE * 4];
__device__ float g_h1[(size_t)NE * HIDF];
__device__ float g_msgh[(size_t)NE * HIDF];
__device__ float g_hneigh[(size_t)NN * HIDF];
__device__ float g_xsum[NN * 3];
__device__ float g_deg[NN];
__device__ float g_hn1[(size_t)NN * HIDF];
__device__ float g_colsum[OUTF];
__device__ float g_colsq[OUTF];

// ---------------- edge geometry ----------------
__global__ void k_geom(const float* __restrict__ coord,
                       const int* __restrict__ src,
                       const int* __restrict__ dst) {
    int e = blockIdx.x * blockDim.x + threadIdx.x;
    if (e >= NE) return;
    int s = src[e], d = dst[e];
    float ax = coord[s * 3 + 0], ay = coord[s * 3 + 1], az = coord[s * 3 + 2];
    float bx = coord[d * 3 + 0], by = coord[d * 3 + 1], bz = coord[d * 3 + 2];
    float dx = ax - bx, dy = ay - by, dz = az - bz;
    float r = dx * dx + dy * dy + dz * dz;
    float inv = 1.0f / (sqrtf(r) + 1e-30f);
    ((float4*)g_xdiff)[e] = make_float4(dx * inv, dy * inv, dz * inv, r);
    atomicAdd(&g_deg[d], 1.0f);
}

// ---------------- GEMM 1: h1 = silu([nf[src], nf[dst], radial] @ W_e1 + b) ----------------
__global__ __launch_bounds__(256, 2)
void k_e1(const float* __restrict__ nf, const int* __restrict__ src,
          const int* __restrict__ dst, const float* __restrict__ W,
          const float* __restrict__ b) {
    __shared__ float As[TBK][128 + 4];
    __shared__ float Bs[TBK][128 + 4];
    __shared__ int s_src[128];
    __shared__ int s_dst[128];
    __shared__ float s_rad[128];
    const int tid = threadIdx.x;
    const int row0 = blockIdx.x * 128;
    const int col0 = blockIdx.y * 128;
    if (tid < 128) {
        int e = row0 + tid;
        s_src[tid] = src[e];
        s_dst[tid] = dst[e];
        s_rad[tid] = g_xdiff[e * 4 + 3];
    }
    __syncthreads();
    const int tx = tid & 15;
    const int ty = tid >> 4;
    u64 acc2[8][4];
#pragma unroll
    for (int i = 0; i < 8; i++)
#pragma unroll
        for (int j = 0; j < 4; j++) acc2[i][j] = 0ull;

    const int nkt = (KE1 + TBK - 1) / TBK;  // 17
    for (int kt = 0; kt < nkt; kt++) {
#pragma unroll
        for (int i = 0; i < 2; i++) {
            int f = tid + i * 256;
            int r = f >> 2;
            int kk = (f & 3) << 2;
            int kg = kt * TBK + kk;
            float4 v = make_float4(0.f, 0.f, 0.f, 0.f);
            if (kg + 3 < 2 * INF) {
                const float* p = (kg < INF) ? (nf + s_src[r] * INF + kg)
                                            : (nf + s_dst[r] * INF + (kg - INF));
                v = *(const float4*)p;
            } else if (kg == 2 * INF) {
                v.x = s_rad[r];
            }
            As[kk + 0][r] = v.x; As[kk + 1][r] = v.y;
            As[kk + 2][r] = v.z; As[kk + 3][r] = v.w;
        }
#pragma unroll
        for (int i = 0; i < 2; i++) {
            int f = tid + i * 256;
            int kk = f >> 5;
            int c = (f & 31) << 2;
            int kg = kt * TBK + kk;
            float4 v = make_float4(0.f, 0.f, 0.f, 0.f);
            if (kg < KE1) v = *(const float4*)(W + (size_t)kg * HIDF + col0 + c);
            *(float4*)&Bs[kk][c] = v;
        }
        __syncthreads();
#pragma unroll
        for (int k = 0; k < TBK; k++)
            mt_step(acc2, &As[k][0], &Bs[k][0], ty * 8, tx * 8);
        __syncthreads();
    }
    float bb[8];
#pragma unroll
    for (int j = 0; j < 8; j++) bb[j] = b[col0 + tx * 8 + j];
#pragma unroll
    for (int i = 0; i < 8; i++) {
        int e = row0 + ty * 8 + i;
        float v[8];
#pragma unroll
        for (int jp = 0; jp < 4; jp++) upk2(acc2[i][jp], v[2 * jp], v[2 * jp + 1]);
        float4 o0, o1;
        o0.x = silu_f(v[0] + bb[0]); o0.y = silu_f(v[1] + bb[1]);
        o0.z = silu_f(v[2] + bb[2]); o0.w = silu_f(v[3] + bb[3]);
        o1.x = silu_f(v[4] + bb[4]); o1.y = silu_f(v[5] + bb[5]);
        o1.z = silu_f(v[6] + bb[6]); o1.w = silu_f(v[7] + bb[7]);
        *(float4*)(g_h1 + (size_t)e * HIDF + col0 + tx * 8) = o0;
        *(float4*)(g_h1 + (size_t)e * HIDF + col0 + tx * 8 + 4) = o1;
    }
}

// ---------------- GEMM 2: msg_h = silu(h1 @ W_e2 + b); aggregate into h_neigh[dst] ----------------
__global__ __launch_bounds__(256, 2)
void k_e2(const int* __restrict__ dst, const float* __restrict__ W,
          const float* __restrict__ b) {
    __shared__ float As[TBK][128 + 4];
    __shared__ float Bs[TBK][128 + 4];
    __shared__ int s_dst[128];
    const int tid = threadIdx.x;
    const int row0 = blockIdx.x * 128;
    const int col0 = blockIdx.y * 128;
    if (tid < 128) s_dst[tid] = dst[row0 + tid];
    __syncthreads();
    const int tx = tid & 15;
    const int ty = tid >> 4;
    u64 acc2[8][4];
#pragma unroll
    for (int i = 0; i < 8; i++)
#pragma unroll
        for (int j = 0; j < 4; j++) acc2[i][j] = 0ull;

    for (int kt = 0; kt < HIDF / TBK; kt++) {
#pragma unroll
        for (int i = 0; i < 2; i++) {
            int f = tid + i * 256;
            int r = f >> 2;
            int kk = (f & 3) << 2;
            float4 v = *(const float4*)(g_h1 + (size_t)(row0 + r) * HIDF + kt * TBK + kk);
            As[kk + 0][r] = v.x; As[kk + 1][r] = v.y;
            As[kk + 2][r] = v.z; As[kk + 3][r] = v.w;
        }
#pragma unroll
        for (int i = 0; i < 2; i++) {
            int f = tid + i * 256;
            int kk = f >> 5;
            int c = (f & 31) << 2;
            *(float4*)&Bs[kk][c] =
                *(const float4*)(W + (size_t)(kt * TBK + kk) * HIDF + col0 + c);
        }
        __syncthreads();
#pragma unroll
        for (int k = 0; k < TBK; k++)
            mt_step(acc2, &As[k][0], &Bs[k][0], ty * 8, tx * 8);
        __syncthreads();
    }
    float bb[8];
#pragma unroll
    for (int j = 0; j < 8; j++) bb[j] = b[col0 + tx * 8 + j];
#pragma unroll
    for (int i = 0; i < 8; i++) {
        int e = row0 + ty * 8 + i;
        int d = s_dst[ty * 8 + i];
        float a[8], v[8];
#pragma unroll
        for (int jp = 0; jp < 4; jp++) upk2(acc2[i][jp], a[2 * jp], a[2 * jp + 1]);
#pragma unroll
        for (int j = 0; j < 8; j++) v[j] = silu_f(a[j] + bb[j]);
        *(float4*)(g_msgh + (size_t)e * HIDF + col0 + tx * 8) =
            make_float4(v[0], v[1], v[2], v[3]);
        *(float4*)(g_msgh + (size_t)e * HIDF + col0 + tx * 8 + 4) =
            make_float4(v[4], v[5], v[6], v[7]);
        float* hn = g_hneigh + (size_t)d * HIDF + col0 + tx * 8;
        red_v4(hn, v[0], v[1], v[2], v[3]);
        red_v4(hn + 4, v[4], v[5], v[6], v[7]);
    }
}

// ---------------- coord GEMM: s = silu(msg_h @ W_c1 + b) . W_c2 ; x_sum[dst] += s * xdiff ----------------
__global__ __launch_bounds__(256, 2)
void k_c(const int* __restrict__ dst, const float* __restrict__ W,
         const float* __restrict__ b, const float* __restrict__ Wc2) {
    __shared__ float As[TBK][64 + 4];
    __shared__ float Bs[TBK][256];
    __shared__ float s_w2[256];
    __shared__ float red[64];
    __shared__ int s_dst[64];
    const int tid = threadIdx.x;
    const int row0 = blockIdx.x * 64;
    s_w2[tid] = Wc2[tid];
    if (tid < 64) s_dst[tid] = dst[row0 + tid];
    __syncthreads();
    const int tx = tid & 31;
    const int ty = tid >> 5;
    u64 acc2[8][4];
#pragma unroll
    for (int i = 0; i < 8; i++)
#pragma unroll
        for (int j = 0; j < 4; j++) acc2[i][j] = 0ull;

    for (int kt = 0; kt < HIDF / TBK; kt++) {
        {
            int f = tid;
            int r = f >> 2;
            int kk = (f & 3) << 2;
            float4 v = *(const float4*)(g_msgh + (size_t)(row0 + r) * HIDF + kt * TBK + kk);
            As[kk + 0][r] = v.x; As[kk + 1][r] = v.y;
            As[kk + 2][r] = v.z; As[kk + 3][r] = v.w;
        }
#pragma unroll
        for (int i = 0; i < 4; i++) {
            int f = tid + i * 256;
            int kk = f >> 6;
            int c = (f & 63) << 2;
            *(float4*)&Bs[kk][c] =
                *(const float4*)(W + (size_t)(kt * TBK + kk) * HIDF + c);
        }
        __syncthreads();
#pragma unroll
        for (int k = 0; k < TBK; k++)
            mt_step(acc2, &As[k][0], &Bs[k][0], ty * 8, tx * 8);
        __syncthreads();
    }
#pragma unroll
    for (int i = 0; i < 8; i++) {
        float a[8];
#pragma unroll
        for (int jp = 0; jp < 4; jp++) upk2(acc2[i][jp], a[2 * jp], a[2 * jp + 1]);
        float s = 0.0f;
#pragma unroll
        for (int j = 0; j < 8; j++) {
            int c = tx * 8 + j;
            s += silu_f(a[j] + b[c]) * s_w2[c];
        }
#pragma unroll
        for (int off = 16; off; off >>= 1) s += __shfl_xor_sync(0xffffffffu, s, off);
        if (tx == 0) red[ty * 8 + i] = s;
    }
    __syncthreads();
    if (tid < 64) {
        int e = row0 + tid;
        float s = red[tid];
        float4 xd = *(const float4*)(g_xdiff + (size_t)e * 4);
        int d = s_dst[tid];
        atomicAdd(&g_xsum[d * 3 + 0], s * xd.x);
        atomicAdd(&g_xsum[d * 3 + 1], s * xd.y);
        atomicAdd(&g_xsum[d * 3 + 2], s * xd.z);
    }
}

// ---------------- node GEMM 1: hn1 = silu([nf, h_neigh] @ W_n1 + b) ----------------
__global__ __launch_bounds__(256, 2)
void k_n1(const float* __restrict__ nf, const float* __restrict__ W,
          const float* __restrict__ b) {
    __shared__ float As[TBK][128 + 4];
    __shared__ float Bs[TBK][128 + 4];
    const int tid = threadIdx.x;
    const int row0 = blockIdx.x * 128;
    const int col0 = blockIdx.y * 128;
    const int tx = tid & 15;
    const int ty = tid >> 4;
    u64 acc2[8][4];
#pragma unroll
    for (int i = 0; i < 8; i++)
#pragma unroll
        for (int j = 0; j < 4; j++) acc2[i][j] = 0ull;

    for (int kt = 0; kt < KN1 / TBK; kt++) {  // 24
#pragma unroll
        for (int i = 0; i < 2; i++) {
            int f = tid + i * 256;
            int r = f >> 2;
            int kk = (f & 3) << 2;
            int kg = kt * TBK + kk;
            int rr = min(row0 + r, NN - 1);
            float4 v;
            if (kg < INF)
                v = *(const float4*)(nf + (size_t)rr * INF + kg);
            else
                v = *(const float4*)(g_hneigh + (size_t)rr * HIDF + (kg - INF));
            As[kk + 0][r] = v.x; As[kk + 1][r] = v.y;
            As[kk + 2][r] = v.z; As[kk + 3][r] = v.w;
        }
#pragma unroll
        for (int i = 0; i < 2; i++) {
            int f = tid + i * 256;
            int kk = f >> 5;
            int c = (f & 31) << 2;
            *(float4*)&Bs[kk][c] =
                *(const float4*)(W + (size_t)(kt * TBK + kk) * HIDF + col0 + c);
        }
        __syncthreads();
#pragma unroll
        for (int k = 0; k < TBK; k++)
            mt_step(acc2, &As[k][0], &Bs[k][0], ty * 8, tx * 8);
        __syncthreads();
    }
    float bb[8];
#pragma unroll
    for (int j = 0; j < 8; j++) bb[j] = b[col0 + tx * 8 + j];
#pragma unroll
    for (int i = 0; i < 8; i++) {
        int row = row0 + ty * 8 + i;
        if (row < NN) {
            float a[8];
#pragma unroll
            for (int jp = 0; jp < 4; jp++) upk2(acc2[i][jp], a[2 * jp], a[2 * jp + 1]);
            float4 o0, o1;
            o0.x = silu_f(a[0] + bb[0]); o0.y = silu_f(a[1] + bb[1]);
            o0.z = silu_f(a[2] + bb[2]); o0.w = silu_f(a[3] + bb[3]);
            o1.x = silu_f(a[4] + bb[4]); o1.y = silu_f(a[5] + bb[5]);
            o1.z = silu_f(a[6] + bb[6]); o1.w = silu_f(a[7] + bb[7]);
            *(float4*)(g_hn1 + (size_t)row * HIDF + col0 + tx * 8) = o0;
            *(float4*)(g_hn1 + (size_t)row * HIDF + col0 + tx * 8 + 4) = o1;
        }
    }
}

// ---------------- node GEMM 2: h = hn1 @ W_n2 + b ; write pre-BN h and column stats ----------------
__global__ __launch_bounds__(256, 2)
void k_n2(const float* __restrict__ W, const float* __restrict__ b,
          float* __restrict__ out) {
    __shared__ float As[TBK][128 + 4];
    __shared__ float Bs[TBK][128 + 4];
    __shared__ float csum[128];
    __shared__ float csq[128];
    const int tid = threadIdx.x;
    const int row0 = blockIdx.x * 128;
    if (tid < 128) { csum[tid] = 0.0f; csq[tid] = 0.0f; }
    const int tx = tid & 15;
    const int ty = tid >> 4;
    u64 acc2[8][4];
#pragma unroll
    for (int i = 0; i < 8; i++)
#pragma unroll
        for (int j = 0; j < 4; j++) acc2[i][j] = 0ull;

    for (int kt = 0; kt < HIDF / TBK; kt++) {
#pragma unroll
        for (int i = 0; i < 2; i++) {
            int f = tid + i * 256;
            int r = f >> 2;
            int kk = (f & 3) << 2;
            int rr = min(row0 + r, NN - 1);
            float4 v = *(const float4*)(g_hn1 + (size_t)rr * HIDF + kt * TBK + kk);
            As[kk + 0][r] = v.x; As[kk + 1][r] = v.y;
            As[kk + 2][r] = v.z; As[kk + 3][r] = v.w;
        }
#pragma unroll
        for (int i = 0; i < 2; i++) {
            int f = tid + i * 256;
            int kk = f >> 5;
            int c = (f & 31) << 2;
            *(float4*)&Bs[kk][c] =
                *(const float4*)(W + (size_t)(kt * TBK + kk) * OUTF + c);
        }
        __syncthreads();
#pragma unroll
        for (int k = 0; k < TBK; k++)
            mt_step(acc2, &As[k][0], &Bs[k][0], ty * 8, tx * 8);
        __syncthreads();
    }
    float bb[8];
#pragma unroll
    for (int j = 0; j < 8; j++) bb[j] = b[tx * 8 + j];
    float cs[8], cq[8];
#pragma unroll
    for (int j = 0; j < 8; j++) { cs[j] = 0.0f; cq[j] = 0.0f; }
#pragma unroll
    for (int i = 0; i < 8; i++) {
        int row = row0 + ty * 8 + i;
        if (row < NN) {
            float a[8], h[8];
#pragma unroll
            for (int jp = 0; jp < 4; jp++) upk2(acc2[i][jp], a[2 * jp], a[2 * jp + 1]);
#pragma unroll
            for (int j = 0; j < 8; j++) {
                h[j] = a[j] + bb[j];
                cs[j] += h[j];
                cq[j] += h[j] * h[j];
            }
            *(float4*)(out + (size_t)row * OUTF + tx * 8) =
                make_float4(h[0], h[1], h[2], h[3]);
            *(float4*)(out + (size_t)row * OUTF + tx * 8 + 4) =
                make_float4(h[4], h[5], h[6], h[7]);
        }
    }
#pragma unroll
    for (int j = 0; j < 8; j++) {
        atomicAdd(&csum[tx * 8 + j], cs[j]);
        atomicAdd(&csq[tx * 8 + j], cq[j]);
    }
    __syncthreads();
    if (tid < 128) {
        atomicAdd(&g_colsum[tid], csum[tid]);
        atomicAdd(&g_colsq[tid], csq[tid]);
    }
}

// ---------------- x output ----------------
__global__ void k_xout(const float* __restrict__ coord, float* __restrict__ out) {
    int n = blockIdx.x * blockDim.x + threadIdx.x;
    if (n >= NN) return;
    float inv = 1.0f / fmaxf(g_deg[n], 1.0f);
    float* o = out + (size_t)NN * OUTF + n * 3;
    o[0] = coord[n * 3 + 0] + g_xsum[n * 3 + 0] * inv;
    o[1] = coord[n * 3 + 1] + g_xsum[n * 3 + 1] * inv;
    o[2] = coord[n * 3 + 2] + g_xsum[n * 3 + 2] * inv;
}

// ---------------- BatchNorm finalize ----------------
__global__ void k_bn(const float* __restrict__ gamma, const float* __restrict__ beta,
                     float* __restrict__ out) {
    int idx = blockIdx.x * blockDim.x + threadIdx.x;
    if (idx >= NN * OUTF) return;
    int c = idx & (OUTF - 1);
    const float invN = 1.0f / (float)NN;
    float mu = g_colsum[c] * invN;
    float var = g_colsq[c] * invN - mu * mu;
    float h = out[idx];
    out[idx] = (h - mu) * rsqrtf(var + 1e-5f) * gamma[c] + beta[c];
}

// ---------------- launch ----------------
extern "C" void kernel_launch(void* const* d_in, const int* in_sizes, int n_in,
                              void* d_out, int out_size) {
    const float* nf    = (const float*)d_in[0];
    const float* coord = (const float*)d_in[1];
    const int*   src   = (const int*)d_in[2];
    const int*   dst   = (const int*)d_in[3];
    const float* We1   = (const float*)d_in[4];
    const float* be1   = (const float*)d_in[5];
    const float* We2   = (const float*)d_in[6];
    const float* be2   = (const float*)d_in[7];
    const float* Wc1   = (const float*)d_in[8];
    const float* bc1   = (const float*)d_in[9];
    const float* Wc2   = (const float*)d_in[10];
    const float* Wn1   = (const float*)d_in[11];
    const float* bn1   = (const float*)d_in[12];
    const float* Wn2   = (const float*)d_in[13];
    const float* bn2   = (const float*)d_in[14];
    const float* gamma = (const float*)d_in[15];
    const float* beta  = (const float*)d_in[16];
    float* out = (float*)d_out;

    void* p;
    cudaGetSymbolAddress(&p, g_hneigh);
    cudaMemsetAsync(p, 0, sizeof(float) * (size_t)NN * HIDF);
    cudaGetSymbolAddress(&p, g_xsum);
    cudaMemsetAsync(p, 0, sizeof(float) * NN * 3);
    cudaGetSymbolAddress(&p, g_deg);
    cudaMemsetAsync(p, 0, sizeof(float) * NN);
    cudaGetSymbolAddress(&p, g_colsum);
    cudaMemsetAsync(p, 0, sizeof(float) * OUTF);
    cudaGetSymbolAddress(&p, g_colsq);
    cudaMemsetAsync(p, 0, sizeof(float) * OUTF);

    k_geom<<<(NE + 255) / 256, 256>>>(coord, src, dst);

    dim3 ge(NE / 128, HIDF / 128);  // (6250, 2)
    k_e1<<<ge, 256>>>(nf, src, dst, We1, be1);
    k_e2<<<ge, 256>>>(dst, We2, be2);
    k_c<<<NE / 64, 256>>>(dst, Wc1, bc1, Wc2);

    dim3 gn((NN + 127) / 128, HIDF / 128);  // (391, 2)
    k_n1<<<gn, 256>>>(nf, Wn1, bn1);
    k_n2<<<(NN + 127) / 128, 256>>>(Wn2, bn2, out);

    k_xout<<<(NN + 255) / 256, 256>>>(coord, out);
    k_bn<<<(NN * OUTF + 255) / 256, 256>>>(gamma, beta, out);
}

// round 3
// speedup vs baseline: 1.4078x; 1.2746x over previous
#include <cuda_runtime.h>
#include <math.h>

#define NN 50000
#define NE 800000
#define INF 128
#define HIDF 256
#define OUTF 128
#define KN1 384   // IN + HID
#define TBK 16

typedef unsigned long long u64;

__device__ __forceinline__ float silu_f(float x) {
    return x * (1.0f / (1.0f + __expf(-x)));
}

// ---- packed f32x2 helpers (sm_100+) ----
__device__ __forceinline__ u64 pk2(float lo, float hi) {
    u64 r;
    asm("mov.b64 %0, {%1, %2};" : "=l"(r) : "f"(lo), "f"(hi));
    return r;
}
__device__ __forceinline__ u64 pkb(float x) {
    u64 r;
    asm("mov.b64 %0, {%1, %1};" : "=l"(r) : "f"(x));
    return r;
}
__device__ __forceinline__ void upk2(u64 v, float& lo, float& hi) {
    asm("mov.b64 {%0, %1}, %2;" : "=f"(lo), "=f"(hi) : "l"(v));
}
__device__ __forceinline__ void fma2(u64& acc, u64 a, u64 b) {
    asm("fma.rn.f32x2 %0, %1, %2, %0;" : "+l"(acc) : "l"(a), "l"(b));
}

__device__ __forceinline__ void mt_step(u64 (&acc2)[8][4], const float* __restrict__ Arow,
                                        const float* __restrict__ Brow, int ty8, int tx8) {
    float4 a0 = *(const float4*)(Arow + ty8);
    float4 a1 = *(const float4*)(Arow + ty8 + 4);
    float4 b0 = *(const float4*)(Brow + tx8);
    float4 b1 = *(const float4*)(Brow + tx8 + 4);
    float ar[8] = {a0.x, a0.y, a0.z, a0.w, a1.x, a1.y, a1.z, a1.w};
    u64 br2[4] = {pk2(b0.x, b0.y), pk2(b0.z, b0.w), pk2(b1.x, b1.y), pk2(b1.z, b1.w)};
#pragma unroll
    for (int i = 0; i < 8; i++) {
        u64 aa = pkb(ar[i]);
#pragma unroll
        for (int jp = 0; jp < 4; jp++) fma2(acc2[i][jp], aa, br2[jp]);
    }
}

__device__ __forceinline__ void red_v4(float* p, float a, float b, float c, float d) {
    asm volatile("red.global.add.v4.f32 [%0], {%1, %2, %3, %4};"
                 :: "l"(p), "f"(a), "f"(b), "f"(c), "f"(d) : "memory");
}

// ---------------- scratch ----------------
__device__ float g_xdiff[NE * 4];
__device__ float g_pa[(size_t)NN * HIDF];   // nf @ W_e1[0:128]
__device__ float g_pb[(size_t)NN * HIDF];   // nf @ W_e1[128:256]
__device__ float g_msgh[(size_t)NE * HIDF];
__device__ float g_hneigh[(size_t)NN * HIDF];
__device__ float g_xsum[NN * 3];
__device__ float g_deg[NN];
__device__ float g_hn1[(size_t)NN * HIDF];
__device__ float g_colsum[OUTF];
__device__ float g_colsq[OUTF];

// ---------------- edge geometry ----------------
__global__ void k_geom(const float* __restrict__ coord,
                       const int* __restrict__ src,
                       const int* __restrict__ dst) {
    int e = blockIdx.x * blockDim.x + threadIdx.x;
    if (e >= NE) return;
    int s = src[e], d = dst[e];
    float ax = coord[s * 3 + 0], ay = coord[s * 3 + 1], az = coord[s * 3 + 2];
    float bx = coord[d * 3 + 0], by = coord[d * 3 + 1], bz = coord[d * 3 + 2];
    float dx = ax - bx, dy = ay - by, dz = az - bz;
    float r = dx * dx + dy * dy + dz * dz;
    float inv = 1.0f / (sqrtf(r) + 1e-30f);
    ((float4*)g_xdiff)[e] = make_float4(dx * inv, dy * inv, dz * inv, r);
    atomicAdd(&g_deg[d], 1.0f);
}

// ---------------- node pre-GEMM: P_a = nf@W_a, P_b = nf@W_b ----------------
// blockIdx.z: 0 -> P_a (W rows [0,128)), 1 -> P_b (W rows [128,256))
__global__ __launch_bounds__(256, 2)
void k_pre(const float* __restrict__ nf, const float* __restrict__ W) {
    __shared__ float As[TBK][128 + 4];
    __shared__ float Bs[TBK][128 + 4];
    const int tid = threadIdx.x;
    const int row0 = blockIdx.x * 128;
    const int col0 = blockIdx.y * 128;
    const float* Wz = W + (size_t)blockIdx.z * INF * HIDF;
    float* out = blockIdx.z ? g_pb : g_pa;
    const int tx = tid & 15;
    const int ty = tid >> 4;
    u64 acc2[8][4];
#pragma unroll
    for (int i = 0; i < 8; i++)
#pragma unroll
        for (int j = 0; j < 4; j++) acc2[i][j] = 0ull;

    for (int kt = 0; kt < INF / TBK; kt++) {  // 8
#pragma unroll
        for (int i = 0; i < 2; i++) {
            int f = tid + i * 256;
            int r = f >> 2;
            int kk = (f & 3) << 2;
            int rr = min(row0 + r, NN - 1);
            float4 v = *(const float4*)(nf + (size_t)rr * INF + kt * TBK + kk);
            As[kk + 0][r] = v.x; As[kk + 1][r] = v.y;
            As[kk + 2][r] = v.z; As[kk + 3][r] = v.w;
        }
#pragma unroll
        for (int i = 0; i < 2; i++) {
            int f = tid + i * 256;
            int kk = f >> 5;
            int c = (f & 31) << 2;
            *(float4*)&Bs[kk][c] =
                *(const float4*)(Wz + (size_t)(kt * TBK + kk) * HIDF + col0 + c);
        }
        __syncthreads();
#pragma unroll
        for (int k = 0; k < TBK; k++)
            mt_step(acc2, &As[k][0], &Bs[k][0], ty * 8, tx * 8);
        __syncthreads();
    }
#pragma unroll
    for (int i = 0; i < 8; i++) {
        int row = row0 + ty * 8 + i;
        if (row < NN) {
            float a[8];
#pragma unroll
            for (int jp = 0; jp < 4; jp++) upk2(acc2[i][jp], a[2 * jp], a[2 * jp + 1]);
            *(float4*)(out + (size_t)row * HIDF + col0 + tx * 8) =
                make_float4(a[0], a[1], a[2], a[3]);
            *(float4*)(out + (size_t)row * HIDF + col0 + tx * 8 + 4) =
                make_float4(a[4], a[5], a[6], a[7]);
        }
    }
}

// ---------------- fused edge GEMM2: msg_h = silu( silu(P_a[src]+P_b[dst]+rad*w_r+b1) @ W_e2 + b2 )
//                  with h_neigh[dst] += msg_h ----------------
__global__ __launch_bounds__(256, 2)
void k_e2(const int* __restrict__ src, const int* __restrict__ dst,
          const float* __restrict__ W1row, const float* __restrict__ b1,
          const float* __restrict__ W, const float* __restrict__ b) {
    __shared__ float As[TBK][128 + 4];
    __shared__ float Bs[TBK][128 + 4];
    __shared__ int s_src[128];
    __shared__ int s_dst[128];
    __shared__ float s_rad[128];
    __shared__ float s_wr[HIDF];
    __shared__ float s_b1[HIDF];
    const int tid = threadIdx.x;
    const int row0 = blockIdx.x * 128;
    const int col0 = blockIdx.y * 128;
    if (tid < 128) {
        int e = row0 + tid;
        s_src[tid] = src[e];
        s_dst[tid] = dst[e];
        s_rad[tid] = g_xdiff[e * 4 + 3];
    }
    s_wr[tid] = W1row[tid];   // W_e1 row 256 (256 floats)
    s_b1[tid] = b1[tid];
    __syncthreads();
    const int tx = tid & 15;
    const int ty = tid >> 4;
    u64 acc2[8][4];
#pragma unroll
    for (int i = 0; i < 8; i++)
#pragma unroll
        for (int j = 0; j < 4; j++) acc2[i][j] = 0ull;

    for (int kt = 0; kt < HIDF / TBK; kt++) {
#pragma unroll
        for (int i = 0; i < 2; i++) {
            int f = tid + i * 256;
            int r = f >> 2;
            int kk = (f & 3) << 2;
            int kg = kt * TBK + kk;
            float4 va = *(const float4*)(g_pa + (size_t)s_src[r] * HIDF + kg);
            float4 vb = *(const float4*)(g_pb + (size_t)s_dst[r] * HIDF + kg);
            float rad = s_rad[r];
            As[kk + 0][r] = silu_f(va.x + vb.x + rad * s_wr[kg + 0] + s_b1[kg + 0]);
            As[kk + 1][r] = silu_f(va.y + vb.y + rad * s_wr[kg + 1] + s_b1[kg + 1]);
            As[kk + 2][r] = silu_f(va.z + vb.z + rad * s_wr[kg + 2] + s_b1[kg + 2]);
            As[kk + 3][r] = silu_f(va.w + vb.w + rad * s_wr[kg + 3] + s_b1[kg + 3]);
        }
#pragma unroll
        for (int i = 0; i < 2; i++) {
            int f = tid + i * 256;
            int kk = f >> 5;
            int c = (f & 31) << 2;
            *(float4*)&Bs[kk][c] =
                *(const float4*)(W + (size_t)(kt * TBK + kk) * HIDF + col0 + c);
        }
        __syncthreads();
#pragma unroll
        for (int k = 0; k < TBK; k++)
            mt_step(acc2, &As[k][0], &Bs[k][0], ty * 8, tx * 8);
        __syncthreads();
    }
    float bb[8];
#pragma unroll
    for (int j = 0; j < 8; j++) bb[j] = b[col0 + tx * 8 + j];
#pragma unroll
    for (int i = 0; i < 8; i++) {
        int e = row0 + ty * 8 + i;
        int d = s_dst[ty * 8 + i];
        float a[8], v[8];
#pragma unroll
        for (int jp = 0; jp < 4; jp++) upk2(acc2[i][jp], a[2 * jp], a[2 * jp + 1]);
#pragma unroll
        for (int j = 0; j < 8; j++) v[j] = silu_f(a[j] + bb[j]);
        *(float4*)(g_msgh + (size_t)e * HIDF + col0 + tx * 8) =
            make_float4(v[0], v[1], v[2], v[3]);
        *(float4*)(g_msgh + (size_t)e * HIDF + col0 + tx * 8 + 4) =
            make_float4(v[4], v[5], v[6], v[7]);
        float* hn = g_hneigh + (size_t)d * HIDF + col0 + tx * 8;
        red_v4(hn, v[0], v[1], v[2], v[3]);
        red_v4(hn + 4, v[4], v[5], v[6], v[7]);
    }
}

// ---------------- coord GEMM ----------------
__global__ __launch_bounds__(256, 2)
void k_c(const int* __restrict__ dst, const float* __restrict__ W,
         const float* __restrict__ b, const float* __restrict__ Wc2) {
    __shared__ float As[TBK][64 + 4];
    __shared__ float Bs[TBK][256];
    __shared__ float s_w2[256];
    __shared__ float red[64];
    __shared__ int s_dst[64];
    const int tid = threadIdx.x;
    const int row0 = blockIdx.x * 64;
    s_w2[tid] = Wc2[tid];
    if (tid < 64) s_dst[tid] = dst[row0 + tid];
    __syncthreads();
    const int tx = tid & 31;
    const int ty = tid >> 5;
    u64 acc2[8][4];
#pragma unroll
    for (int i = 0; i < 8; i++)
#pragma unroll
        for (int j = 0; j < 4; j++) acc2[i][j] = 0ull;

    for (int kt = 0; kt < HIDF / TBK; kt++) {
        {
            int f = tid;
            int r = f >> 2;
            int kk = (f & 3) << 2;
            float4 v = *(const float4*)(g_msgh + (size_t)(row0 + r) * HIDF + kt * TBK + kk);
            As[kk + 0][r] = v.x; As[kk + 1][r] = v.y;
            As[kk + 2][r] = v.z; As[kk + 3][r] = v.w;
        }
#pragma unroll
        for (int i = 0; i < 4; i++) {
            int f = tid + i * 256;
            int kk = f >> 6;
            int c = (f & 63) << 2;
            *(float4*)&Bs[kk][c] =
                *(const float4*)(W + (size_t)(kt * TBK + kk) * HIDF + c);
        }
        __syncthreads();
#pragma unroll
        for (int k = 0; k < TBK; k++)
            mt_step(acc2, &As[k][0], &Bs[k][0], ty * 8, tx * 8);
        __syncthreads();
    }
#pragma unroll
    for (int i = 0; i < 8; i++) {
        float a[8];
#pragma unroll
        for (int jp = 0; jp < 4; jp++) upk2(acc2[i][jp], a[2 * jp], a[2 * jp + 1]);
        float s = 0.0f;
#pragma unroll
        for (int j = 0; j < 8; j++) {
            int c = tx * 8 + j;
            s += silu_f(a[j] + b[c]) * s_w2[c];
        }
#pragma unroll
        for (int off = 16; off; off >>= 1) s += __shfl_xor_sync(0xffffffffu, s, off);
        if (tx == 0) red[ty * 8 + i] = s;
    }
    __syncthreads();
    if (tid < 64) {
        int e = row0 + tid;
        float s = red[tid];
        float4 xd = *(const float4*)(g_xdiff + (size_t)e * 4);
        int d = s_dst[tid];
        atomicAdd(&g_xsum[d * 3 + 0], s * xd.x);
        atomicAdd(&g_xsum[d * 3 + 1], s * xd.y);
        atomicAdd(&g_xsum[d * 3 + 2], s * xd.z);
    }
}

// ---------------- node GEMM 1 ----------------
__global__ __launch_bounds__(256, 2)
void k_n1(const float* __restrict__ nf, const float* __restrict__ W,
          const float* __restrict__ b) {
    __shared__ float As[TBK][128 + 4];
    __shared__ float Bs[TBK][128 + 4];
    const int tid = threadIdx.x;
    const int row0 = blockIdx.x * 128;
    const int col0 = blockIdx.y * 128;
    const int tx = tid & 15;
    const int ty = tid >> 4;
    u64 acc2[8][4];
#pragma unroll
    for (int i = 0; i < 8; i++)
#pragma unroll
        for (int j = 0; j < 4; j++) acc2[i][j] = 0ull;

    for (int kt = 0; kt < KN1 / TBK; kt++) {
#pragma unroll
        for (int i = 0; i < 2; i++) {
            int f = tid + i * 256;
            int r = f >> 2;
            int kk = (f & 3) << 2;
            int kg = kt * TBK + kk;
            int rr = min(row0 + r, NN - 1);
            float4 v;
            if (kg < INF)
                v = *(const float4*)(nf + (size_t)rr * INF + kg);
            else
                v = *(const float4*)(g_hneigh + (size_t)rr * HIDF + (kg - INF));
            As[kk + 0][r] = v.x; As[kk + 1][r] = v.y;
            As[kk + 2][r] = v.z; As[kk + 3][r] = v.w;
        }
#pragma unroll
        for (int i = 0; i < 2; i++) {
            int f = tid + i * 256;
            int kk = f >> 5;
            int c = (f & 31) << 2;
            *(float4*)&Bs[kk][c] =
                *(const float4*)(W + (size_t)(kt * TBK + kk) * HIDF + col0 + c);
        }
        __syncthreads();
#pragma unroll
        for (int k = 0; k < TBK; k++)
            mt_step(acc2, &As[k][0], &Bs[k][0], ty * 8, tx * 8);
        __syncthreads();
    }
    float bb[8];
#pragma unroll
    for (int j = 0; j < 8; j++) bb[j] = b[col0 + tx * 8 + j];
#pragma unroll
    for (int i = 0; i < 8; i++) {
        int row = row0 + ty * 8 + i;
        if (row < NN) {
            float a[8];
#pragma unroll
            for (int jp = 0; jp < 4; jp++) upk2(acc2[i][jp], a[2 * jp], a[2 * jp + 1]);
            float4 o0, o1;
            o0.x = silu_f(a[0] + bb[0]); o0.y = silu_f(a[1] + bb[1]);
            o0.z = silu_f(a[2] + bb[2]); o0.w = silu_f(a[3] + bb[3]);
            o1.x = silu_f(a[4] + bb[4]); o1.y = silu_f(a[5] + bb[5]);
            o1.z = silu_f(a[6] + bb[6]); o1.w = silu_f(a[7] + bb[7]);
            *(float4*)(g_hn1 + (size_t)row * HIDF + col0 + tx * 8) = o0;
            *(float4*)(g_hn1 + (size_t)row * HIDF + col0 + tx * 8 + 4) = o1;
        }
    }
}

// ---------------- node GEMM 2 + BN stats ----------------
__global__ __launch_bounds__(256, 2)
void k_n2(const float* __restrict__ W, const float* __restrict__ b,
          float* __restrict__ out) {
    __shared__ float As[TBK][128 + 4];
    __shared__ float Bs[TBK][128 + 4];
    __shared__ float csum[128];
    __shared__ float csq[128];
    const int tid = threadIdx.x;
    const int row0 = blockIdx.x * 128;
    if (tid < 128) { csum[tid] = 0.0f; csq[tid] = 0.0f; }
    const int tx = tid & 15;
    const int ty = tid >> 4;
    u64 acc2[8][4];
#pragma unroll
    for (int i = 0; i < 8; i++)
#pragma unroll
        for (int j = 0; j < 4; j++) acc2[i][j] = 0ull;

    for (int kt = 0; kt < HIDF / TBK; kt++) {
#pragma unroll
        for (int i = 0; i < 2; i++) {
            int f = tid + i * 256;
            int r = f >> 2;
            int kk = (f & 3) << 2;
            int rr = min(row0 + r, NN - 1);
            float4 v = *(const float4*)(g_hn1 + (size_t)rr * HIDF + kt * TBK + kk);
            As[kk + 0][r] = v.x; As[kk + 1][r] = v.y;
            As[kk + 2][r] = v.z; As[kk + 3][r] = v.w;
        }
#pragma unroll
        for (int i = 0; i < 2; i++) {
            int f = tid + i * 256;
            int kk = f >> 5;
            int c = (f & 31) << 2;
            *(float4*)&Bs[kk][c] =
                *(const float4*)(W + (size_t)(kt * TBK + kk) * OUTF + c);
        }
        __syncthreads();
#pragma unroll
        for (int k = 0; k < TBK; k++)
            mt_step(acc2, &As[k][0], &Bs[k][0], ty * 8, tx * 8);
        __syncthreads();
    }
    float bb[8];
#pragma unroll
    for (int j = 0; j < 8; j++) bb[j] = b[tx * 8 + j];
    float cs[8], cq[8];
#pragma unroll
    for (int j = 0; j < 8; j++) { cs[j] = 0.0f; cq[j] = 0.0f; }
#pragma unroll
    for (int i = 0; i < 8; i++) {
        int row = row0 + ty * 8 + i;
        if (row < NN) {
            float a[8], h[8];
#pragma unroll
            for (int jp = 0; jp < 4; jp++) upk2(acc2[i][jp], a[2 * jp], a[2 * jp + 1]);
#pragma unroll
            for (int j = 0; j < 8; j++) {
                h[j] = a[j] + bb[j];
                cs[j] += h[j];
                cq[j] += h[j] * h[j];
            }
            *(float4*)(out + (size_t)row * OUTF + tx * 8) =
                make_float4(h[0], h[1], h[2], h[3]);
            *(float4*)(out + (size_t)row * OUTF + tx * 8 + 4) =
                make_float4(h[4], h[5], h[6], h[7]);
        }
    }
#pragma unroll
    for (int j = 0; j < 8; j++) {
        atomicAdd(&csum[tx * 8 + j], cs[j]);
        atomicAdd(&csq[tx * 8 + j], cq[j]);
    }
    __syncthreads();
    if (tid < 128) {
        atomicAdd(&g_colsum[tid], csum[tid]);
        atomicAdd(&g_colsq[tid], csq[tid]);
    }
}

// ---------------- x output ----------------
__global__ void k_xout(const float* __restrict__ coord, float* __restrict__ out) {
    int n = blockIdx.x * blockDim.x + threadIdx.x;
    if (n >= NN) return;
    float inv = 1.0f / fmaxf(g_deg[n], 1.0f);
    float* o = out + (size_t)NN * OUTF + n * 3;
    o[0] = coord[n * 3 + 0] + g_xsum[n * 3 + 0] * inv;
    o[1] = coord[n * 3 + 1] + g_xsum[n * 3 + 1] * inv;
    o[2] = coord[n * 3 + 2] + g_xsum[n * 3 + 2] * inv;
}

// ---------------- BatchNorm finalize ----------------
__global__ void k_bn(const float* __restrict__ gamma, const float* __restrict__ beta,
                     float* __restrict__ out) {
    int idx = blockIdx.x * blockDim.x + threadIdx.x;
    if (idx >= NN * OUTF) return;
    int c = idx & (OUTF - 1);
    const float invN = 1.0f / (float)NN;
    float mu = g_colsum[c] * invN;
    float var = g_colsq[c] * invN - mu * mu;
    float h = out[idx];
    out[idx] = (h - mu) * rsqrtf(var + 1e-5f) * gamma[c] + beta[c];
}

// ---------------- launch ----------------
extern "C" void kernel_launch(void* const* d_in, const int* in_sizes, int n_in,
                              void* d_out, int out_size) {
    const float* nf    = (const float*)d_in[0];
    const float* coord = (const float*)d_in[1];
    const int*   src   = (const int*)d_in[2];
    const int*   dst   = (const int*)d_in[3];
    const float* We1   = (const float*)d_in[4];
    const float* be1   = (const float*)d_in[5];
    const float* We2   = (const float*)d_in[6];
    const float* be2   = (const float*)d_in[7];
    const float* Wc1   = (const float*)d_in[8];
    const float* bc1   = (const float*)d_in[9];
    const float* Wc2   = (const float*)d_in[10];
    const float* Wn1   = (const float*)d_in[11];
    const float* bn1   = (const float*)d_in[12];
    const float* Wn2   = (const float*)d_in[13];
    const float* bn2   = (const float*)d_in[14];
    const float* gamma = (const float*)d_in[15];
    const float* beta  = (const float*)d_in[16];
    float* out = (float*)d_out;

    void* p;
    cudaGetSymbolAddress(&p, g_hneigh);
    cudaMemsetAsync(p, 0, sizeof(float) * (size_t)NN * HIDF);
    cudaGetSymbolAddress(&p, g_xsum);
    cudaMemsetAsync(p, 0, sizeof(float) * NN * 3);
    cudaGetSymbolAddress(&p, g_deg);
    cudaMemsetAsync(p, 0, sizeof(float) * NN);
    cudaGetSymbolAddress(&p, g_colsum);
    cudaMemsetAsync(p, 0, sizeof(float) * OUTF);
    cudaGetSymbolAddress(&p, g_colsq);
    cudaMemsetAsync(p, 0, sizeof(float) * OUTF);

    k_geom<<<(NE + 255) / 256, 256>>>(coord, src, dst);

    dim3 gp((NN + 127) / 128, HIDF / 128, 2);  // (391, 2, 2)
    k_pre<<<gp, 256>>>(nf, We1);

    dim3 ge(NE / 128, HIDF / 128);  // (6250, 2)
    k_e2<<<ge, 256>>>(src, dst, We1 + (size_t)2 * INF * HIDF, be1, We2, be2);
    k_c<<<NE / 64, 256>>>(dst, Wc1, bc1, Wc2);

    dim3 gn((NN + 127) / 128, HIDF / 128);  // (391, 2)
    k_n1<<<gn, 256>>>(nf, Wn1, bn1);
    k_n2<<<(NN + 127) / 128, 256>>>(Wn2, bn2, out);

    k_xout<<<(NN + 255) / 256, 256>>>(coord, out);
    k_bn<<<(NN * OUTF + 255) / 256, 256>>>(gamma, beta, out);
}

// round 4
// speedup vs baseline: 2.2859x; 1.6237x over previous
#include <cuda_runtime.h>
#include <math.h>
#include <stdint.h>

#define NN 50000
#define NE 800000
#define INF 128
#define HIDF 256
#define OUTF 128
#define KN1 384   // IN + HID
#define TBK 16

typedef unsigned long long u64;

__device__ __forceinline__ float silu_f(float x) {
    return x * (1.0f / (1.0f + __expf(-x)));
}

// ---- packed f32x2 helpers (sm_100+) ----
__device__ __forceinline__ u64 pk2(float lo, float hi) {
    u64 r;
    asm("mov.b64 %0, {%1, %2};" : "=l"(r) : "f"(lo), "f"(hi));
    return r;
}
__device__ __forceinline__ u64 pkb(float x) {
    u64 r;
    asm("mov.b64 %0, {%1, %1};" : "=l"(r) : "f"(x));
    return r;
}
__device__ __forceinline__ void upk2(u64 v, float& lo, float& hi) {
    asm("mov.b64 {%0, %1}, %2;" : "=f"(lo), "=f"(hi) : "l"(v));
}
__device__ __forceinline__ void fma2(u64& acc, u64 a, u64 b) {
    asm("fma.rn.f32x2 %0, %1, %2, %0;" : "+l"(acc) : "l"(a), "l"(b));
}

__device__ __forceinline__ void mt_step(u64 (&acc2)[8][4], const float* __restrict__ Arow,
                                        const float* __restrict__ Brow, int ty8, int tx8) {
    float4 a0 = *(const float4*)(Arow + ty8);
    float4 a1 = *(const float4*)(Arow + ty8 + 4);
    float4 b0 = *(const float4*)(Brow + tx8);
    float4 b1 = *(const float4*)(Brow + tx8 + 4);
    float ar[8] = {a0.x, a0.y, a0.z, a0.w, a1.x, a1.y, a1.z, a1.w};
    u64 br2[4] = {pk2(b0.x, b0.y), pk2(b0.z, b0.w), pk2(b1.x, b1.y), pk2(b1.z, b1.w)};
#pragma unroll
    for (int i = 0; i < 8; i++) {
        u64 aa = pkb(ar[i]);
#pragma unroll
        for (int jp = 0; jp < 4; jp++) fma2(acc2[i][jp], aa, br2[jp]);
    }
}

// ---- tf32 mma helpers ----
__device__ __forceinline__ uint32_t f2tf(float x) {
    uint32_t r;
    asm("cvt.rna.tf32.f32 %0, %1;" : "=r"(r) : "f"(x));
    return r;
}
__device__ __forceinline__ void mma_tf32(float (&c)[4], const uint32_t (&a)[4],
                                         const uint32_t (&b)[2]) {
    asm("mma.sync.aligned.m16n8k8.row.col.f32.tf32.tf32.f32 "
        "{%0,%1,%2,%3}, {%4,%5,%6,%7}, {%8,%9}, {%0,%1,%2,%3};"
        : "+f"(c[0]), "+f"(c[1]), "+f"(c[2]), "+f"(c[3])
        : "r"(a[0]), "r"(a[1]), "r"(a[2]), "r"(a[3]), "r"(b[0]), "r"(b[1]));
}

__device__ __forceinline__ void red_v2(float* p, float a, float b) {
    asm volatile("red.global.add.v2.f32 [%0], {%1, %2};"
                 :: "l"(p), "f"(a), "f"(b) : "memory");
}

// ---------------- scratch ----------------
__device__ float g_xdiff[NE * 4];
__device__ float g_pa[(size_t)NN * HIDF];
__device__ float g_pb[(size_t)NN * HIDF];
__device__ float g_msgh[(size_t)NE * HIDF];
__device__ float g_hneigh[(size_t)NN * HIDF];
__device__ float g_xsum[NN * 3];
__device__ float g_deg[NN];
__device__ float g_hn1[(size_t)NN * HIDF];
__device__ float g_colsum[OUTF];
__device__ float g_colsq[OUTF];

// ---------------- edge geometry ----------------
__global__ void k_geom(const float* __restrict__ coord,
                       const int* __restrict__ src,
                       const int* __restrict__ dst) {
    int e = blockIdx.x * blockDim.x + threadIdx.x;
    if (e >= NE) return;
    int s = src[e], d = dst[e];
    float ax = coord[s * 3 + 0], ay = coord[s * 3 + 1], az = coord[s * 3 + 2];
    float bx = coord[d * 3 + 0], by = coord[d * 3 + 1], bz = coord[d * 3 + 2];
    float dx = ax - bx, dy = ay - by, dz = az - bz;
    float r = dx * dx + dy * dy + dz * dz;
    float inv = 1.0f / (sqrtf(r) + 1e-30f);
    ((float4*)g_xdiff)[e] = make_float4(dx * inv, dy * inv, dz * inv, r);
    atomicAdd(&g_deg[d], 1.0f);
}

// ---------------- node pre-GEMM: P_a = nf@W_a, P_b = nf@W_b (fp32) ----------------
__global__ __launch_bounds__(256, 2)
void k_pre(const float* __restrict__ nf, const float* __restrict__ W) {
    __shared__ float As[TBK][128 + 4];
    __shared__ float Bs[TBK][128 + 4];
    const int tid = threadIdx.x;
    const int row0 = blockIdx.x * 128;
    const int col0 = blockIdx.y * 128;
    const float* Wz = W + (size_t)blockIdx.z * INF * HIDF;
    float* out = blockIdx.z ? g_pb : g_pa;
    const int tx = tid & 15;
    const int ty = tid >> 4;
    u64 acc2[8][4];
#pragma unroll
    for (int i = 0; i < 8; i++)
#pragma unroll
        for (int j = 0; j < 4; j++) acc2[i][j] = 0ull;

    for (int kt = 0; kt < INF / TBK; kt++) {
#pragma unroll
        for (int i = 0; i < 2; i++) {
            int f = tid + i * 256;
            int r = f >> 2;
            int kk = (f & 3) << 2;
            int rr = min(row0 + r, NN - 1);
            float4 v = *(const float4*)(nf + (size_t)rr * INF + kt * TBK + kk);
            As[kk + 0][r] = v.x; As[kk + 1][r] = v.y;
            As[kk + 2][r] = v.z; As[kk + 3][r] = v.w;
        }
#pragma unroll
        for (int i = 0; i < 2; i++) {
            int f = tid + i * 256;
            int kk = f >> 5;
            int c = (f & 31) << 2;
            *(float4*)&Bs[kk][c] =
                *(const float4*)(Wz + (size_t)(kt * TBK + kk) * HIDF + col0 + c);
        }
        __syncthreads();
#pragma unroll
        for (int k = 0; k < TBK; k++)
            mt_step(acc2, &As[k][0], &Bs[k][0], ty * 8, tx * 8);
        __syncthreads();
    }
#pragma unroll
    for (int i = 0; i < 8; i++) {
        int row = row0 + ty * 8 + i;
        if (row < NN) {
            float a[8];
#pragma unroll
            for (int jp = 0; jp < 4; jp++) upk2(acc2[i][jp], a[2 * jp], a[2 * jp + 1]);
            *(float4*)(out + (size_t)row * HIDF + col0 + tx * 8) =
                make_float4(a[0], a[1], a[2], a[3]);
            *(float4*)(out + (size_t)row * HIDF + col0 + tx * 8 + 4) =
                make_float4(a[4], a[5], a[6], a[7]);
        }
    }
}

// ---------------- fused edge GEMM2 (tf32 tensor cores) ----------------
// msg_h = silu( silu(P_a[src]+P_b[dst]+rad*w_r+b1) @ W_e2 + b2 ); h_neigh[dst] += msg_h
__global__ __launch_bounds__(256, 2)
void k_e2(const int* __restrict__ src, const int* __restrict__ dst,
          const float* __restrict__ W1row, const float* __restrict__ b1,
          const float* __restrict__ W, const float* __restrict__ b2) {
    __shared__ uint32_t As[TBK][128 + 8];   // stride 136: conflict-free frag loads
    __shared__ uint32_t Bs[TBK][128 + 8];
    __shared__ int s_src[128];
    __shared__ int s_dst[128];
    __shared__ float s_rad[128];
    __shared__ float s_wr[HIDF];
    __shared__ float s_b1[HIDF];
    __shared__ float s_b2[128];
    const int tid = threadIdx.x;
    const int row0 = blockIdx.x * 128;
    const int col0 = blockIdx.y * 128;
    if (tid < 128) {
        int e = row0 + tid;
        s_src[tid] = src[e];
        s_dst[tid] = dst[e];
        s_rad[tid] = g_xdiff[e * 4 + 3];
        s_b2[tid] = b2[col0 + tid];
    }
    s_wr[tid] = W1row[tid];
    s_b1[tid] = b1[tid];
    __syncthreads();
    const int lane = tid & 31;
    const int g = lane >> 2;
    const int tig = lane & 3;
    const int wid = tid >> 5;
    const int wr = wid >> 2;   // 0..1 -> 64 rows each
    const int wc = wid & 3;    // 0..3 -> 32 cols each
    float c[4][4][4];
#pragma unroll
    for (int mt = 0; mt < 4; mt++)
#pragma unroll
        for (int nt = 0; nt < 4; nt++)
#pragma unroll
            for (int q = 0; q < 4; q++) c[mt][nt][q] = 0.0f;

    for (int kt = 0; kt < HIDF / TBK; kt++) {
        // A staging: gather + silu + tf32 cvt
#pragma unroll
        for (int i = 0; i < 2; i++) {
            int f = tid + i * 256;
            int r = f >> 2;
            int kk = (f & 3) << 2;
            int kg = kt * TBK + kk;
            float4 va = *(const float4*)(g_pa + (size_t)s_src[r] * HIDF + kg);
            float4 vb = *(const float4*)(g_pb + (size_t)s_dst[r] * HIDF + kg);
            float rad = s_rad[r];
            As[kk + 0][r] = f2tf(silu_f(va.x + vb.x + rad * s_wr[kg + 0] + s_b1[kg + 0]));
            As[kk + 1][r] = f2tf(silu_f(va.y + vb.y + rad * s_wr[kg + 1] + s_b1[kg + 1]));
            As[kk + 2][r] = f2tf(silu_f(va.z + vb.z + rad * s_wr[kg + 2] + s_b1[kg + 2]));
            As[kk + 3][r] = f2tf(silu_f(va.w + vb.w + rad * s_wr[kg + 3] + s_b1[kg + 3]));
        }
        // B staging: tf32 cvt
#pragma unroll
        for (int i = 0; i < 2; i++) {
            int f = tid + i * 256;
            int kk = f >> 5;
            int cc = (f & 31) << 2;
            float4 v = *(const float4*)(W + (size_t)(kt * TBK + kk) * HIDF + col0 + cc);
            Bs[kk][cc + 0] = f2tf(v.x); Bs[kk][cc + 1] = f2tf(v.y);
            Bs[kk][cc + 2] = f2tf(v.z); Bs[kk][cc + 3] = f2tf(v.w);
        }
        __syncthreads();
#pragma unroll
        for (int ks = 0; ks < TBK; ks += 8) {
            uint32_t af[4][4], bf[4][2];
#pragma unroll
            for (int mt = 0; mt < 4; mt++) {
                int rb = wr * 64 + mt * 16;
                af[mt][0] = As[ks + tig][rb + g];
                af[mt][1] = As[ks + tig][rb + g + 8];
                af[mt][2] = As[ks + tig + 4][rb + g];
                af[mt][3] = As[ks + tig + 4][rb + g + 8];
            }
#pragma unroll
            for (int nt = 0; nt < 4; nt++) {
                int cb = wc * 32 + nt * 8;
                bf[nt][0] = Bs[ks + tig][cb + g];
                bf[nt][1] = Bs[ks + tig + 4][cb + g];
            }
#pragma unroll
            for (int mt = 0; mt < 4; mt++)
#pragma unroll
                for (int nt = 0; nt < 4; nt++)
                    mma_tf32(c[mt][nt], af[mt], bf[nt]);
        }
        __syncthreads();
    }
    // epilogue: bias + silu, store msg_h, reduce into h_neigh
#pragma unroll
    for (int mt = 0; mt < 4; mt++) {
        int r1 = wr * 64 + mt * 16 + g;
        int r2 = r1 + 8;
        int e1 = row0 + r1, e2 = row0 + r2;
        int d1 = s_dst[r1], d2 = s_dst[r2];
#pragma unroll
        for (int nt = 0; nt < 4; nt++) {
            int lc = wc * 32 + nt * 8 + tig * 2;
            float v0 = silu_f(c[mt][nt][0] + s_b2[lc]);
            float v1 = silu_f(c[mt][nt][1] + s_b2[lc + 1]);
            float v2 = silu_f(c[mt][nt][2] + s_b2[lc]);
            float v3 = silu_f(c[mt][nt][3] + s_b2[lc + 1]);
            *(float2*)(g_msgh + (size_t)e1 * HIDF + col0 + lc) = make_float2(v0, v1);
            *(float2*)(g_msgh + (size_t)e2 * HIDF + col0 + lc) = make_float2(v2, v3);
            red_v2(g_hneigh + (size_t)d1 * HIDF + col0 + lc, v0, v1);
            red_v2(g_hneigh + (size_t)d2 * HIDF + col0 + lc, v2, v3);
        }
    }
}

// ---------------- coord GEMM (tf32): s = silu(msg_h @ W_c1 + b) . W_c2 ; scatter ----------------
__global__ __launch_bounds__(256, 2)
void k_c(const int* __restrict__ dst, const float* __restrict__ W,
         const float* __restrict__ b, const float* __restrict__ Wc2) {
    __shared__ uint32_t As[TBK][64 + 8];    // stride 72
    __shared__ uint32_t Bs[TBK][256 + 8];   // stride 264
    __shared__ float s_w2[256];
    __shared__ float s_b1[256];
    __shared__ float red[64];
    __shared__ int s_dst[64];
    const int tid = threadIdx.x;
    const int row0 = blockIdx.x * 64;
    s_w2[tid] = Wc2[tid];
    s_b1[tid] = b[tid];
    if (tid < 64) {
        s_dst[tid] = dst[row0 + tid];
        red[tid] = 0.0f;
    }
    __syncthreads();
    const int lane = tid & 31;
    const int g = lane >> 2;
    const int tig = lane & 3;
    const int wid = tid >> 5;
    const int wr = wid >> 2;   // 0..1 -> 32 rows each
    const int wc = wid & 3;    // 0..3 -> 64 cols each
    float c[2][8][4];
#pragma unroll
    for (int mt = 0; mt < 2; mt++)
#pragma unroll
        for (int nt = 0; nt < 8; nt++)
#pragma unroll
            for (int q = 0; q < 4; q++) c[mt][nt][q] = 0.0f;

    for (int kt = 0; kt < HIDF / TBK; kt++) {
        {
            int r = tid >> 2;
            int kk = (tid & 3) << 2;
            float4 v = *(const float4*)(g_msgh + (size_t)(row0 + r) * HIDF + kt * TBK + kk);
            As[kk + 0][r] = f2tf(v.x); As[kk + 1][r] = f2tf(v.y);
            As[kk + 2][r] = f2tf(v.z); As[kk + 3][r] = f2tf(v.w);
        }
#pragma unroll
        for (int i = 0; i < 4; i++) {
            int f = tid + i * 256;
            int kk = f >> 6;
            int cc = (f & 63) << 2;
            float4 v = *(const float4*)(W + (size_t)(kt * TBK + kk) * HIDF + cc);
            Bs[kk][cc + 0] = f2tf(v.x); Bs[kk][cc + 1] = f2tf(v.y);
            Bs[kk][cc + 2] = f2tf(v.z); Bs[kk][cc + 3] = f2tf(v.w);
        }
        __syncthreads();
#pragma unroll
        for (int ks = 0; ks < TBK; ks += 8) {
            uint32_t af[2][4], bf[8][2];
#pragma unroll
            for (int mt = 0; mt < 2; mt++) {
                int rb = wr * 32 + mt * 16;
                af[mt][0] = As[ks + tig][rb + g];
                af[mt][1] = As[ks + tig][rb + g + 8];
                af[mt][2] = As[ks + tig + 4][rb + g];
                af[mt][3] = As[ks + tig + 4][rb + g + 8];
            }
#pragma unroll
            for (int nt = 0; nt < 8; nt++) {
                int cb = wc * 64 + nt * 8;
                bf[nt][0] = Bs[ks + tig][cb + g];
                bf[nt][1] = Bs[ks + tig + 4][cb + g];
            }
#pragma unroll
            for (int mt = 0; mt < 2; mt++)
#pragma unroll
                for (int nt = 0; nt < 8; nt++)
                    mma_tf32(c[mt][nt], af[mt], bf[nt]);
        }
        __syncthreads();
    }
    // epilogue: silu + dot with w2, reduce per row
#pragma unroll
    for (int mt = 0; mt < 2; mt++) {
        float s1 = 0.0f, s2 = 0.0f;
#pragma unroll
        for (int nt = 0; nt < 8; nt++) {
            int lc = wc * 64 + nt * 8 + tig * 2;
            s1 += silu_f(c[mt][nt][0] + s_b1[lc]) * s_w2[lc]
                + silu_f(c[mt][nt][1] + s_b1[lc + 1]) * s_w2[lc + 1];
            s2 += silu_f(c[mt][nt][2] + s_b1[lc]) * s_w2[lc]
                + silu_f(c[mt][nt][3] + s_b1[lc + 1]) * s_w2[lc + 1];
        }
        s1 += __shfl_xor_sync(0xffffffffu, s1, 1);
        s1 += __shfl_xor_sync(0xffffffffu, s1, 2);
        s2 += __shfl_xor_sync(0xffffffffu, s2, 1);
        s2 += __shfl_xor_sync(0xffffffffu, s2, 2);
        if (tig == 0) {
            atomicAdd(&red[wr * 32 + mt * 16 + g], s1);
            atomicAdd(&red[wr * 32 + mt * 16 + g + 8], s2);
        }
    }
    __syncthreads();
    if (tid < 64) {
        int e = row0 + tid;
        float s = red[tid];
        float4 xd = *(const float4*)(g_xdiff + (size_t)e * 4);
        int d = s_dst[tid];
        atomicAdd(&g_xsum[d * 3 + 0], s * xd.x);
        atomicAdd(&g_xsum[d * 3 + 1], s * xd.y);
        atomicAdd(&g_xsum[d * 3 + 2], s * xd.z);
    }
}

// ---------------- node GEMM 1 (fp32) ----------------
__global__ __launch_bounds__(256, 2)
void k_n1(const float* __restrict__ nf, const float* __restrict__ W,
          const float* __restrict__ b) {
    __shared__ float As[TBK][128 + 4];
    __shared__ float Bs[TBK][128 + 4];
    const int tid = threadIdx.x;
    const int row0 = blockIdx.x * 128;
    const int col0 = blockIdx.y * 128;
    const int tx = tid & 15;
    const int ty = tid >> 4;
    u64 acc2[8][4];
#pragma unroll
    for (int i = 0; i < 8; i++)
#pragma unroll
        for (int j = 0; j < 4; j++) acc2[i][j] = 0ull;

    for (int kt = 0; kt < KN1 / TBK; kt++) {
#pragma unroll
        for (int i = 0; i < 2; i++) {
            int f = tid + i * 256;
            int r = f >> 2;
            int kk = (f & 3) << 2;
            int kg = kt * TBK + kk;
            int rr = min(row0 + r, NN - 1);
            float4 v;
            if (kg < INF)
                v = *(const float4*)(nf + (size_t)rr * INF + kg);
            else
                v = *(const float4*)(g_hneigh + (size_t)rr * HIDF + (kg - INF));
            As[kk + 0][r] = v.x; As[kk + 1][r] = v.y;
            As[kk + 2][r] = v.z; As[kk + 3][r] = v.w;
        }
#pragma unroll
        for (int i = 0; i < 2; i++) {
            int f = tid + i * 256;
            int kk = f >> 5;
            int c = (f & 31) << 2;
            *(float4*)&Bs[kk][c] =
                *(const float4*)(W + (size_t)(kt * TBK + kk) * HIDF + col0 + c);
        }
        __syncthreads();
#pragma unroll
        for (int k = 0; k < TBK; k++)
            mt_step(acc2, &As[k][0], &Bs[k][0], ty * 8, tx * 8);
        __syncthreads();
    }
    float bb[8];
#pragma unroll
    for (int j = 0; j < 8; j++) bb[j] = b[col0 + tx * 8 + j];
#pragma unroll
    for (int i = 0; i < 8; i++) {
        int row = row0 + ty * 8 + i;
        if (row < NN) {
            float a[8];
#pragma unroll
            for (int jp = 0; jp < 4; jp++) upk2(acc2[i][jp], a[2 * jp], a[2 * jp + 1]);
            float4 o0, o1;
            o0.x = silu_f(a[0] + bb[0]); o0.y = silu_f(a[1] + bb[1]);
            o0.z = silu_f(a[2] + bb[2]); o0.w = silu_f(a[3] + bb[3]);
            o1.x = silu_f(a[4] + bb[4]); o1.y = silu_f(a[5] + bb[5]);
            o1.z = silu_f(a[6] + bb[6]); o1.w = silu_f(a[7] + bb[7]);
            *(float4*)(g_hn1 + (size_t)row * HIDF + col0 + tx * 8) = o0;
            *(float4*)(g_hn1 + (size_t)row * HIDF + col0 + tx * 8 + 4) = o1;
        }
    }
}

// ---------------- node GEMM 2 + BN stats (fp32) ----------------
__global__ __launch_bounds__(256, 2)
void k_n2(const float* __restrict__ W, const float* __restrict__ b,
          float* __restrict__ out) {
    __shared__ float As[TBK][128 + 4];
    __shared__ float Bs[TBK][128 + 4];
    __shared__ float csum[128];
    __shared__ float csq[128];
    const int tid = threadIdx.x;
    const int row0 = blockIdx.x * 128;
    if (tid < 128) { csum[tid] = 0.0f; csq[tid] = 0.0f; }
    const int tx = tid & 15;
    const int ty = tid >> 4;
    u64 acc2[8][4];
#pragma unroll
    for (int i = 0; i < 8; i++)
#pragma unroll
        for (int j = 0; j < 4; j++) acc2[i][j] = 0ull;

    for (int kt = 0; kt < HIDF / TBK; kt++) {
#pragma unroll
        for (int i = 0; i < 2; i++) {
            int f = tid + i * 256;
            int r = f >> 2;
            int kk = (f & 3) << 2;
            int rr = min(row0 + r, NN - 1);
            float4 v = *(const float4*)(g_hn1 + (size_t)rr * HIDF + kt * TBK + kk);
            As[kk + 0][r] = v.x; As[kk + 1][r] = v.y;
            As[kk + 2][r] = v.z; As[kk + 3][r] = v.w;
        }
#pragma unroll
        for (int i = 0; i < 2; i++) {
            int f = tid + i * 256;
            int kk = f >> 5;
            int c = (f & 31) << 2;
            *(float4*)&Bs[kk][c] =
                *(const float4*)(W + (size_t)(kt * TBK + kk) * OUTF + c);
        }
        __syncthreads();
#pragma unroll
        for (int k = 0; k < TBK; k++)
            mt_step(acc2, &As[k][0], &Bs[k][0], ty * 8, tx * 8);
        __syncthreads();
    }
    float bb[8];
#pragma unroll
    for (int j = 0; j < 8; j++) bb[j] = b[tx * 8 + j];
    float cs[8], cq[8];
#pragma unroll
    for (int j = 0; j < 8; j++) { cs[j] = 0.0f; cq[j] = 0.0f; }
#pragma unroll
    for (int i = 0; i < 8; i++) {
        int row = row0 + ty * 8 + i;
        if (row < NN) {
            float a[8], h[8];
#pragma unroll
            for (int jp = 0; jp < 4; jp++) upk2(acc2[i][jp], a[2 * jp], a[2 * jp + 1]);
#pragma unroll
            for (int j = 0; j < 8; j++) {
                h[j] = a[j] + bb[j];
                cs[j] += h[j];
                cq[j] += h[j] * h[j];
            }
            *(float4*)(out + (size_t)row * OUTF + tx * 8) =
                make_float4(h[0], h[1], h[2], h[3]);
            *(float4*)(out + (size_t)row * OUTF + tx * 8 + 4) =
                make_float4(h[4], h[5], h[6], h[7]);
        }
    }
#pragma unroll
    for (int j = 0; j < 8; j++) {
        atomicAdd(&csum[tx * 8 + j], cs[j]);
        atomicAdd(&csq[tx * 8 + j], cq[j]);
    }
    __syncthreads();
    if (tid < 128) {
        atomicAdd(&g_colsum[tid], csum[tid]);
        atomicAdd(&g_colsq[tid], csq[tid]);
    }
}

// ---------------- x output ----------------
__global__ void k_xout(const float* __restrict__ coord, float* __restrict__ out) {
    int n = blockIdx.x * blockDim.x + threadIdx.x;
    if (n >= NN) return;
    float inv = 1.0f / fmaxf(g_deg[n], 1.0f);
    float* o = out + (size_t)NN * OUTF + n * 3;
    o[0] = coord[n * 3 + 0] + g_xsum[n * 3 + 0] * inv;
    o[1] = coord[n * 3 + 1] + g_xsum[n * 3 + 1] * inv;
    o[2] = coord[n * 3 + 2] + g_xsum[n * 3 + 2] * inv;
}

// ---------------- BatchNorm finalize ----------------
__global__ void k_bn(const float* __restrict__ gamma, const float* __restrict__ beta,
                     float* __restrict__ out) {
    int idx = blockIdx.x * blockDim.x + threadIdx.x;
    if (idx >= NN * OUTF) return;
    int c = idx & (OUTF - 1);
    const float invN = 1.0f / (float)NN;
    float mu = g_colsum[c] * invN;
    float var = g_colsq[c] * invN - mu * mu;
    float h = out[idx];
    out[idx] = (h - mu) * rsqrtf(var + 1e-5f) * gamma[c] + beta[c];
}

// ---------------- launch ----------------
extern "C" void kernel_launch(void* const* d_in, const int* in_sizes, int n_in,
                              void* d_out, int out_size) {
    const float* nf    = (const float*)d_in[0];
    const float* coord = (const float*)d_in[1];
    const int*   src   = (const int*)d_in[2];
    const int*   dst   = (const int*)d_in[3];
    const float* We1   = (const float*)d_in[4];
    const float* be1   = (const float*)d_in[5];
    const float* We2   = (const float*)d_in[6];
    const float* be2   = (const float*)d_in[7];
    const float* Wc1   = (const float*)d_in[8];
    const float* bc1   = (const float*)d_in[9];
    const float* Wc2   = (const float*)d_in[10];
    const float* Wn1   = (const float*)d_in[11];
    const float* bn1   = (const float*)d_in[12];
    const float* Wn2   = (const float*)d_in[13];
    const float* bn2   = (const float*)d_in[14];
    const float* gamma = (const float*)d_in[15];
    const float* beta  = (const float*)d_in[16];
    float* out = (float*)d_out;

    void* p;
    cudaGetSymbolAddress(&p, g_hneigh);
    cudaMemsetAsync(p, 0, sizeof(float) * (size_t)NN * HIDF);
    cudaGetSymbolAddress(&p, g_xsum);
    cudaMemsetAsync(p, 0, sizeof(float) * NN * 3);
    cudaGetSymbolAddress(&p, g_deg);
    cudaMemsetAsync(p, 0, sizeof(float) * NN);
    cudaGetSymbolAddress(&p, g_colsum);
    cudaMemsetAsync(p, 0, sizeof(float) * OUTF);
    cudaGetSymbolAddress(&p, g_colsq);
    cudaMemsetAsync(p, 0, sizeof(float) * OUTF);

    k_geom<<<(NE + 255) / 256, 256>>>(coord, src, dst);

    dim3 gp((NN + 127) / 128, HIDF / 128, 2);
    k_pre<<<gp, 256>>>(nf, We1);

    dim3 ge(NE / 128, HIDF / 128);
    k_e2<<<ge, 256>>>(src, dst, We1 + (size_t)2 * INF * HIDF, be1, We2, be2);
    k_c<<<NE / 64, 256>>>(dst, Wc1, bc1, Wc2);

    dim3 gn((NN + 127) / 128, HIDF / 128);
    k_n1<<<gn, 256>>>(nf, Wn1, bn1);
    k_n2<<<(NN + 127) / 128, 256>>>(Wn2, bn2, out);

    k_xout<<<(NN + 255) / 256, 256>>>(coord, out);
    k_bn<<<(NN * OUTF + 255) / 256, 256>>>(gamma, beta, out);
}

// round 5
// speedup vs baseline: 2.4875x; 1.0882x over previous
#include <cuda_runtime.h>
#include <math.h>
#include <stdint.h>

#define NN 50000
#define NE 800000
#define INF 128
#define HIDF 256
#define OUTF 128
#define KN1 384   // IN + HID
#define TBK 16

typedef unsigned long long u64;

__device__ __forceinline__ float silu_f(float x) {
    return x * (1.0f / (1.0f + __expf(-x)));
}

// ---- packed f32x2 helpers (sm_100+) ----
__device__ __forceinline__ u64 pk2(float lo, float hi) {
    u64 r;
    asm("mov.b64 %0, {%1, %2};" : "=l"(r) : "f"(lo), "f"(hi));
    return r;
}
__device__ __forceinline__ u64 pkb(float x) {
    u64 r;
    asm("mov.b64 %0, {%1, %1};" : "=l"(r) : "f"(x));
    return r;
}
__device__ __forceinline__ void upk2(u64 v, float& lo, float& hi) {
    asm("mov.b64 {%0, %1}, %2;" : "=f"(lo), "=f"(hi) : "l"(v));
}
__device__ __forceinline__ void fma2(u64& acc, u64 a, u64 b) {
    asm("fma.rn.f32x2 %0, %1, %2, %0;" : "+l"(acc) : "l"(a), "l"(b));
}

__device__ __forceinline__ void mt_step(u64 (&acc2)[8][4], const float* __restrict__ Arow,
                                        const float* __restrict__ Brow, int ty8, int tx8) {
    float4 a0 = *(const float4*)(Arow + ty8);
    float4 a1 = *(const float4*)(Arow + ty8 + 4);
    float4 b0 = *(const float4*)(Brow + tx8);
    float4 b1 = *(const float4*)(Brow + tx8 + 4);
    float ar[8] = {a0.x, a0.y, a0.z, a0.w, a1.x, a1.y, a1.z, a1.w};
    u64 br2[4] = {pk2(b0.x, b0.y), pk2(b0.z, b0.w), pk2(b1.x, b1.y), pk2(b1.z, b1.w)};
#pragma unroll
    for (int i = 0; i < 8; i++) {
        u64 aa = pkb(ar[i]);
#pragma unroll
        for (int jp = 0; jp < 4; jp++) fma2(acc2[i][jp], aa, br2[jp]);
    }
}

// ---- tf32 mma helpers ----
__device__ __forceinline__ uint32_t f2tf(float x) {
    uint32_t r;
    asm("cvt.rna.tf32.f32 %0, %1;" : "=r"(r) : "f"(x));
    return r;
}
__device__ __forceinline__ void mma_tf32(float (&c)[4], const uint32_t (&a)[4],
                                         const uint32_t (&b)[2]) {
    asm("mma.sync.aligned.m16n8k8.row.col.f32.tf32.tf32.f32 "
        "{%0,%1,%2,%3}, {%4,%5,%6,%7}, {%8,%9}, {%0,%1,%2,%3};"
        : "+f"(c[0]), "+f"(c[1]), "+f"(c[2]), "+f"(c[3])
        : "r"(a[0]), "r"(a[1]), "r"(a[2]), "r"(a[3]), "r"(b[0]), "r"(b[1]));
}

__device__ __forceinline__ void red_v2(float* p, float a, float b) {
    asm volatile("red.global.add.v2.f32 [%0], {%1, %2};"
                 :: "l"(p), "f"(a), "f"(b) : "memory");
}

// ---------------- scratch ----------------
__device__ float g_xdiff[NE * 4];
__device__ float g_pa[(size_t)NN * HIDF];
__device__ float g_pb[(size_t)NN * HIDF];
__device__ float g_msgh[(size_t)NE * HIDF];
__device__ float g_hneigh[(size_t)NN * HIDF];
__device__ float g_xsum[NN * 3];
__device__ float g_deg[NN];
__device__ float g_hn1[(size_t)NN * HIDF];
__device__ float g_colsum[OUTF];
__device__ float g_colsq[OUTF];

// ---------------- edge geometry ----------------
__global__ void k_geom(const float* __restrict__ coord,
                       const int* __restrict__ src,
                       const int* __restrict__ dst) {
    int e = blockIdx.x * blockDim.x + threadIdx.x;
    if (e >= NE) return;
    int s = src[e], d = dst[e];
    float ax = coord[s * 3 + 0], ay = coord[s * 3 + 1], az = coord[s * 3 + 2];
    float bx = coord[d * 3 + 0], by = coord[d * 3 + 1], bz = coord[d * 3 + 2];
    float dx = ax - bx, dy = ay - by, dz = az - bz;
    float r = dx * dx + dy * dy + dz * dz;
    float inv = 1.0f / (sqrtf(r) + 1e-30f);
    ((float4*)g_xdiff)[e] = make_float4(dx * inv, dy * inv, dz * inv, r);
    atomicAdd(&g_deg[d], 1.0f);
}

// ---------------- node pre-GEMM: P_a = nf@W_a, P_b = nf@W_b (fp32) ----------------
__global__ __launch_bounds__(256, 2)
void k_pre(const float* __restrict__ nf, const float* __restrict__ W) {
    __shared__ float As[TBK][128 + 4];
    __shared__ float Bs[TBK][128 + 4];
    const int tid = threadIdx.x;
    const int row0 = blockIdx.x * 128;
    const int col0 = blockIdx.y * 128;
    const float* Wz = W + (size_t)blockIdx.z * INF * HIDF;
    float* out = blockIdx.z ? g_pb : g_pa;
    const int tx = tid & 15;
    const int ty = tid >> 4;
    u64 acc2[8][4];
#pragma unroll
    for (int i = 0; i < 8; i++)
#pragma unroll
        for (int j = 0; j < 4; j++) acc2[i][j] = 0ull;

    for (int kt = 0; kt < INF / TBK; kt++) {
#pragma unroll
        for (int i = 0; i < 2; i++) {
            int f = tid + i * 256;
            int r = f >> 2;
            int kk = (f & 3) << 2;
            int rr = min(row0 + r, NN - 1);
            float4 v = *(const float4*)(nf + (size_t)rr * INF + kt * TBK + kk);
            As[kk + 0][r] = v.x; As[kk + 1][r] = v.y;
            As[kk + 2][r] = v.z; As[kk + 3][r] = v.w;
        }
#pragma unroll
        for (int i = 0; i < 2; i++) {
            int f = tid + i * 256;
            int kk = f >> 5;
            int c = (f & 31) << 2;
            *(float4*)&Bs[kk][c] =
                *(const float4*)(Wz + (size_t)(kt * TBK + kk) * HIDF + col0 + c);
        }
        __syncthreads();
#pragma unroll
        for (int k = 0; k < TBK; k++)
            mt_step(acc2, &As[k][0], &Bs[k][0], ty * 8, tx * 8);
        __syncthreads();
    }
#pragma unroll
    for (int i = 0; i < 8; i++) {
        int row = row0 + ty * 8 + i;
        if (row < NN) {
            float a[8];
#pragma unroll
            for (int jp = 0; jp < 4; jp++) upk2(acc2[i][jp], a[2 * jp], a[2 * jp + 1]);
            *(float4*)(out + (size_t)row * HIDF + col0 + tx * 8) =
                make_float4(a[0], a[1], a[2], a[3]);
            *(float4*)(out + (size_t)row * HIDF + col0 + tx * 8 + 4) =
                make_float4(a[4], a[5], a[6], a[7]);
        }
    }
}

// ---------------- fused edge GEMM2 (tf32, 512 threads, 32x32 warp tiles) ----------------
__global__ __launch_bounds__(512, 2)
void k_e2(const int* __restrict__ src, const int* __restrict__ dst,
          const float* __restrict__ W1row, const float* __restrict__ b1,
          const float* __restrict__ W, const float* __restrict__ b2) {
    __shared__ uint32_t As[128][20];       // row-major, pad 20 -> conflict-free frags
    __shared__ uint32_t Bs[TBK][128 + 8];  // stride 136
    __shared__ int s_src[128];
    __shared__ int s_dst[128];
    __shared__ float s_rad[128];
    __shared__ float s_wr[HIDF];
    __shared__ float s_b1[HIDF];
    __shared__ float s_b2[128];
    const int tid = threadIdx.x;
    const int row0 = blockIdx.x * 128;
    const int col0 = blockIdx.y * 128;
    if (tid < 128) {
        int e = row0 + tid;
        s_src[tid] = src[e];
        s_dst[tid] = dst[e];
        s_rad[tid] = g_xdiff[e * 4 + 3];
        s_b2[tid] = b2[col0 + tid];
    }
    if (tid < HIDF) {
        s_wr[tid] = W1row[tid];
        s_b1[tid] = b1[tid];
    }
    __syncthreads();
    const int lane = tid & 31;
    const int g = lane >> 2;
    const int tig = lane & 3;
    const int wid = tid >> 5;
    const int wr = wid >> 2;   // 0..3 -> 32 rows each
    const int wc = wid & 3;    // 0..3 -> 32 cols each
    float c[2][4][4];
#pragma unroll
    for (int mt = 0; mt < 2; mt++)
#pragma unroll
        for (int nt = 0; nt < 4; nt++)
#pragma unroll
            for (int q = 0; q < 4; q++) c[mt][nt][q] = 0.0f;

    for (int kt = 0; kt < HIDF / TBK; kt++) {
        // A staging: 128x16, one float4 per thread; gather + silu + tf32
        {
            int r = tid >> 2;
            int kk = (tid & 3) << 2;
            int kg = kt * TBK + kk;
            float4 va = *(const float4*)(g_pa + (size_t)s_src[r] * HIDF + kg);
            float4 vb = *(const float4*)(g_pb + (size_t)s_dst[r] * HIDF + kg);
            float rad = s_rad[r];
            uint4 o;
            o.x = f2tf(silu_f(va.x + vb.x + rad * s_wr[kg + 0] + s_b1[kg + 0]));
            o.y = f2tf(silu_f(va.y + vb.y + rad * s_wr[kg + 1] + s_b1[kg + 1]));
            o.z = f2tf(silu_f(va.z + vb.z + rad * s_wr[kg + 2] + s_b1[kg + 2]));
            o.w = f2tf(silu_f(va.w + vb.w + rad * s_wr[kg + 3] + s_b1[kg + 3]));
            *(uint4*)&As[r][kk] = o;
        }
        // B staging: 16x128, one float4 per thread
        {
            int kk = tid >> 5;
            int cc = (tid & 31) << 2;
            float4 v = *(const float4*)(W + (size_t)(kt * TBK + kk) * HIDF + col0 + cc);
            uint4 o;
            o.x = f2tf(v.x); o.y = f2tf(v.y); o.z = f2tf(v.z); o.w = f2tf(v.w);
            *(uint4*)&Bs[kk][cc] = o;
        }
        __syncthreads();
#pragma unroll
        for (int ks = 0; ks < TBK; ks += 8) {
            uint32_t af[2][4], bf[4][2];
#pragma unroll
            for (int mt = 0; mt < 2; mt++) {
                int rb = wr * 32 + mt * 16;
                af[mt][0] = As[rb + g][ks + tig];
                af[mt][1] = As[rb + g + 8][ks + tig];
                af[mt][2] = As[rb + g][ks + tig + 4];
                af[mt][3] = As[rb + g + 8][ks + tig + 4];
            }
#pragma unroll
            for (int nt = 0; nt < 4; nt++) {
                int cb = wc * 32 + nt * 8;
                bf[nt][0] = Bs[ks + tig][cb + g];
                bf[nt][1] = Bs[ks + tig + 4][cb + g];
            }
#pragma unroll
            for (int mt = 0; mt < 2; mt++)
#pragma unroll
                for (int nt = 0; nt < 4; nt++)
                    mma_tf32(c[mt][nt], af[mt], bf[nt]);
        }
        __syncthreads();
    }
    // epilogue
#pragma unroll
    for (int mt = 0; mt < 2; mt++) {
        int r1 = wr * 32 + mt * 16 + g;
        int r2 = r1 + 8;
        int e1 = row0 + r1, e2 = row0 + r2;
        int d1 = s_dst[r1], d2 = s_dst[r2];
#pragma unroll
        for (int nt = 0; nt < 4; nt++) {
            int lc = wc * 32 + nt * 8 + tig * 2;
            float v0 = silu_f(c[mt][nt][0] + s_b2[lc]);
            float v1 = silu_f(c[mt][nt][1] + s_b2[lc + 1]);
            float v2 = silu_f(c[mt][nt][2] + s_b2[lc]);
            float v3 = silu_f(c[mt][nt][3] + s_b2[lc + 1]);
            *(float2*)(g_msgh + (size_t)e1 * HIDF + col0 + lc) = make_float2(v0, v1);
            *(float2*)(g_msgh + (size_t)e2 * HIDF + col0 + lc) = make_float2(v2, v3);
            red_v2(g_hneigh + (size_t)d1 * HIDF + col0 + lc, v0, v1);
            red_v2(g_hneigh + (size_t)d2 * HIDF + col0 + lc, v2, v3);
        }
    }
}

// ---------------- coord GEMM (tf32, 512 threads, tile 64x256) ----------------
__global__ __launch_bounds__(512, 2)
void k_c(const int* __restrict__ dst, const float* __restrict__ W,
         const float* __restrict__ b, const float* __restrict__ Wc2) {
    __shared__ uint32_t As[64][20];
    __shared__ uint32_t Bs[TBK][256 + 8];   // stride 264
    __shared__ float s_w2[256];
    __shared__ float s_b1[256];
    __shared__ float red[64];
    __shared__ int s_dst[64];
    const int tid = threadIdx.x;
    const int row0 = blockIdx.x * 64;
    if (tid < 256) {
        s_w2[tid] = Wc2[tid];
        s_b1[tid] = b[tid];
    }
    if (tid < 64) {
        s_dst[tid] = dst[row0 + tid];
        red[tid] = 0.0f;
    }
    __syncthreads();
    const int lane = tid & 31;
    const int g = lane >> 2;
    const int tig = lane & 3;
    const int wid = tid >> 5;
    const int wr = wid >> 3;   // 0..1 -> 32 rows each
    const int wc = wid & 7;    // 0..7 -> 32 cols each
    float c[2][4][4];
#pragma unroll
    for (int mt = 0; mt < 2; mt++)
#pragma unroll
        for (int nt = 0; nt < 4; nt++)
#pragma unroll
            for (int q = 0; q < 4; q++) c[mt][nt][q] = 0.0f;

    for (int kt = 0; kt < HIDF / TBK; kt++) {
        // A: 64x16 = 256 float4
        if (tid < 256) {
            int r = tid >> 2;
            int kk = (tid & 3) << 2;
            float4 v = *(const float4*)(g_msgh + (size_t)(row0 + r) * HIDF + kt * TBK + kk);
            uint4 o;
            o.x = f2tf(v.x); o.y = f2tf(v.y); o.z = f2tf(v.z); o.w = f2tf(v.w);
            *(uint4*)&As[r][kk] = o;
        }
        // B: 16x256 = 1024 float4 -> 2 per thread
#pragma unroll
        for (int i = 0; i < 2; i++) {
            int f = tid + i * 512;
            int kk = f >> 6;
            int cc = (f & 63) << 2;
            float4 v = *(const float4*)(W + (size_t)(kt * TBK + kk) * HIDF + cc);
            uint4 o;
            o.x = f2tf(v.x); o.y = f2tf(v.y); o.z = f2tf(v.z); o.w = f2tf(v.w);
            *(uint4*)&Bs[kk][cc] = o;
        }
        __syncthreads();
#pragma unroll
        for (int ks = 0; ks < TBK; ks += 8) {
            uint32_t af[2][4], bf[4][2];
#pragma unroll
            for (int mt = 0; mt < 2; mt++) {
                int rb = wr * 32 + mt * 16;
                af[mt][0] = As[rb + g][ks + tig];
                af[mt][1] = As[rb + g + 8][ks + tig];
                af[mt][2] = As[rb + g][ks + tig + 4];
                af[mt][3] = As[rb + g + 8][ks + tig + 4];
            }
#pragma unroll
            for (int nt = 0; nt < 4; nt++) {
                int cb = wc * 32 + nt * 8;
                bf[nt][0] = Bs[ks + tig][cb + g];
                bf[nt][1] = Bs[ks + tig + 4][cb + g];
            }
#pragma unroll
            for (int mt = 0; mt < 2; mt++)
#pragma unroll
                for (int nt = 0; nt < 4; nt++)
                    mma_tf32(c[mt][nt], af[mt], bf[nt]);
        }
        __syncthreads();
    }
    // epilogue: silu + dot with w2, reduce over the warp's 32 cols, then cross-warp
#pragma unroll
    for (int mt = 0; mt < 2; mt++) {
        float s1 = 0.0f, s2 = 0.0f;
#pragma unroll
        for (int nt = 0; nt < 4; nt++) {
            int lc = wc * 32 + nt * 8 + tig * 2;
            s1 += silu_f(c[mt][nt][0] + s_b1[lc]) * s_w2[lc]
                + silu_f(c[mt][nt][1] + s_b1[lc + 1]) * s_w2[lc + 1];
            s2 += silu_f(c[mt][nt][2] + s_b1[lc]) * s_w2[lc]
                + silu_f(c[mt][nt][3] + s_b1[lc + 1]) * s_w2[lc + 1];
        }
        s1 += __shfl_xor_sync(0xffffffffu, s1, 1);
        s1 += __shfl_xor_sync(0xffffffffu, s1, 2);
        s2 += __shfl_xor_sync(0xffffffffu, s2, 1);
        s2 += __shfl_xor_sync(0xffffffffu, s2, 2);
        if (tig == 0) {
            atomicAdd(&red[wr * 32 + mt * 16 + g], s1);
            atomicAdd(&red[wr * 32 + mt * 16 + g + 8], s2);
        }
    }
    __syncthreads();
    if (tid < 64) {
        int e = row0 + tid;
        float s = red[tid];
        float4 xd = *(const float4*)(g_xdiff + (size_t)e * 4);
        int d = s_dst[tid];
        atomicAdd(&g_xsum[d * 3 + 0], s * xd.x);
        atomicAdd(&g_xsum[d * 3 + 1], s * xd.y);
        atomicAdd(&g_xsum[d * 3 + 2], s * xd.z);
    }
}

// ---------------- node GEMM 1 (fp32) ----------------
__global__ __launch_bounds__(256, 2)
void k_n1(const float* __restrict__ nf, const float* __restrict__ W,
          const float* __restrict__ b) {
    __shared__ float As[TBK][128 + 4];
    __shared__ float Bs[TBK][128 + 4];
    const int tid = threadIdx.x;
    const int row0 = blockIdx.x * 128;
    const int col0 = blockIdx.y * 128;
    const int tx = tid & 15;
    const int ty = tid >> 4;
    u64 acc2[8][4];
#pragma unroll
    for (int i = 0; i < 8; i++)
#pragma unroll
        for (int j = 0; j < 4; j++) acc2[i][j] = 0ull;

    for (int kt = 0; kt < KN1 / TBK; kt++) {
#pragma unroll
        for (int i = 0; i < 2; i++) {
            int f = tid + i * 256;
            int r = f >> 2;
            int kk = (f & 3) << 2;
            int kg = kt * TBK + kk;
            int rr = min(row0 + r, NN - 1);
            float4 v;
            if (kg < INF)
                v = *(const float4*)(nf + (size_t)rr * INF + kg);
            else
                v = *(const float4*)(g_hneigh + (size_t)rr * HIDF + (kg - INF));
            As[kk + 0][r] = v.x; As[kk + 1][r] = v.y;
            As[kk + 2][r] = v.z; As[kk + 3][r] = v.w;
        }
#pragma unroll
        for (int i = 0; i < 2; i++) {
            int f = tid + i * 256;
            int kk = f >> 5;
            int c = (f & 31) << 2;
            *(float4*)&Bs[kk][c] =
                *(const float4*)(W + (size_t)(kt * TBK + kk) * HIDF + col0 + c);
        }
        __syncthreads();
#pragma unroll
        for (int k = 0; k < TBK; k++)
            mt_step(acc2, &As[k][0], &Bs[k][0], ty * 8, tx * 8);
        __syncthreads();
    }
    float bb[8];
#pragma unroll
    for (int j = 0; j < 8; j++) bb[j] = b[col0 + tx * 8 + j];
#pragma unroll
    for (int i = 0; i < 8; i++) {
        int row = row0 + ty * 8 + i;
        if (row < NN) {
            float a[8];
#pragma unroll
            for (int jp = 0; jp < 4; jp++) upk2(acc2[i][jp], a[2 * jp], a[2 * jp + 1]);
            float4 o0, o1;
            o0.x = silu_f(a[0] + bb[0]); o0.y = silu_f(a[1] + bb[1]);
            o0.z = silu_f(a[2] + bb[2]); o0.w = silu_f(a[3] + bb[3]);
            o1.x = silu_f(a[4] + bb[4]); o1.y = silu_f(a[5] + bb[5]);
            o1.z = silu_f(a[6] + bb[6]); o1.w = silu_f(a[7] + bb[7]);
            *(float4*)(g_hn1 + (size_t)row * HIDF + col0 + tx * 8) = o0;
            *(float4*)(g_hn1 + (size_t)row * HIDF + col0 + tx * 8 + 4) = o1;
        }
    }
}

// ---------------- node GEMM 2 + BN stats (fp32) ----------------
__global__ __launch_bounds__(256, 2)
void k_n2(const float* __restrict__ W, const float* __restrict__ b,
          float* __restrict__ out) {
    __shared__ float As[TBK][128 + 4];
    __shared__ float Bs[TBK][128 + 4];
    __shared__ float csum[128];
    __shared__ float csq[128];
    const int tid = threadIdx.x;
    const int row0 = blockIdx.x * 128;
    if (tid < 128) { csum[tid] = 0.0f; csq[tid] = 0.0f; }
    const int tx = tid & 15;
    const int ty = tid >> 4;
    u64 acc2[8][4];
#pragma unroll
    for (int i = 0; i < 8; i++)
#pragma unroll
        for (int j = 0; j < 4; j++) acc2[i][j] = 0ull;

    for (int kt = 0; kt < HIDF / TBK; kt++) {
#pragma unroll
        for (int i = 0; i < 2; i++) {
            int f = tid + i * 256;
            int r = f >> 2;
            int kk = (f & 3) << 2;
            int rr = min(row0 + r, NN - 1);
            float4 v = *(const float4*)(g_hn1 + (size_t)rr * HIDF + kt * TBK + kk);
            As[kk + 0][r] = v.x; As[kk + 1][r] = v.y;
            As[kk + 2][r] = v.z; As[kk + 3][r] = v.w;
        }
#pragma unroll
        for (int i = 0; i < 2; i++) {
            int f = tid + i * 256;
            int kk = f >> 5;
            int c = (f & 31) << 2;
            *(float4*)&Bs[kk][c] =
                *(const float4*)(W + (size_t)(kt * TBK + kk) * OUTF + c);
        }
        __syncthreads();
#pragma unroll
        for (int k = 0; k < TBK; k++)
            mt_step(acc2, &As[k][0], &Bs[k][0], ty * 8, tx * 8);
        __syncthreads();
    }
    float bb[8];
#pragma unroll
    for (int j = 0; j < 8; j++) bb[j] = b[tx * 8 + j];
    float cs[8], cq[8];
#pragma unroll
    for (int j = 0; j < 8; j++) { cs[j] = 0.0f; cq[j] = 0.0f; }
#pragma unroll
    for (int i = 0; i < 8; i++) {
        int row = row0 + ty * 8 + i;
        if (row < NN) {
            float a[8], h[8];
#pragma unroll
            for (int jp = 0; jp < 4; jp++) upk2(acc2[i][jp], a[2 * jp], a[2 * jp + 1]);
#pragma unroll
            for (int j = 0; j < 8; j++) {
                h[j] = a[j] + bb[j];
                cs[j] += h[j];
                cq[j] += h[j] * h[j];
            }
            *(float4*)(out + (size_t)row * OUTF + tx * 8) =
                make_float4(h[0], h[1], h[2], h[3]);
            *(float4*)(out + (size_t)row * OUTF + tx * 8 + 4) =
                make_float4(h[4], h[5], h[6], h[7]);
        }
    }
#pragma unroll
    for (int j = 0; j < 8; j++) {
        atomicAdd(&csum[tx * 8 + j], cs[j]);
        atomicAdd(&csq[tx * 8 + j], cq[j]);
    }
    __syncthreads();
    if (tid < 128) {
        atomicAdd(&g_colsum[tid], csum[tid]);
        atomicAdd(&g_colsq[tid], csq[tid]);
    }
}

// ---------------- x output ----------------
__global__ void k_xout(const float* __restrict__ coord, float* __restrict__ out) {
    int n = blockIdx.x * blockDim.x + threadIdx.x;
    if (n >= NN) return;
    float inv = 1.0f / fmaxf(g_deg[n], 1.0f);
    float* o = out + (size_t)NN * OUTF + n * 3;
    o[0] = coord[n * 3 + 0] + g_xsum[n * 3 + 0] * inv;
    o[1] = coord[n * 3 + 1] + g_xsum[n * 3 + 1] * inv;
    o[2] = coord[n * 3 + 2] + g_xsum[n * 3 + 2] * inv;
}

// ---------------- BatchNorm finalize ----------------
__global__ void k_bn(const float* __restrict__ gamma, const float* __restrict__ beta,
                     float* __restrict__ out) {
    int idx = blockIdx.x * blockDim.x + threadIdx.x;
    if (idx >= NN * OUTF) return;
    int c = idx & (OUTF - 1);
    const float invN = 1.0f / (float)NN;
    float mu = g_colsum[c] * invN;
    float var = g_colsq[c] * invN - mu * mu;
    float h = out[idx];
    out[idx] = (h - mu) * rsqrtf(var + 1e-5f) * gamma[c] + beta[c];
}

// ---------------- launch ----------------
extern "C" void kernel_launch(void* const* d_in, const int* in_sizes, int n_in,
                              void* d_out, int out_size) {
    const float* nf    = (const float*)d_in[0];
    const float* coord = (const float*)d_in[1];
    const int*   src   = (const int*)d_in[2];
    const int*   dst   = (const int*)d_in[3];
    const float* We1   = (const float*)d_in[4];
    const float* be1   = (const float*)d_in[5];
    const float* We2   = (const float*)d_in[6];
    const float* be2   = (const float*)d_in[7];
    const float* Wc1   = (const float*)d_in[8];
    const float* bc1   = (const float*)d_in[9];
    const float* Wc2   = (const float*)d_in[10];
    const float* Wn1   = (const float*)d_in[11];
    const float* bn1   = (const float*)d_in[12];
    const float* Wn2   = (const float*)d_in[13];
    const float* bn2   = (const float*)d_in[14];
    const float* gamma = (const float*)d_in[15];
    const float* beta  = (const float*)d_in[16];
    float* out = (float*)d_out;

    void* p;
    cudaGetSymbolAddress(&p, g_hneigh);
    cudaMemsetAsync(p, 0, sizeof(float) * (size_t)NN * HIDF);
    cudaGetSymbolAddress(&p, g_xsum);
    cudaMemsetAsync(p, 0, sizeof(float) * NN * 3);
    cudaGetSymbolAddress(&p, g_deg);
    cudaMemsetAsync(p, 0, sizeof(float) * NN);
    cudaGetSymbolAddress(&p, g_colsum);
    cudaMemsetAsync(p, 0, sizeof(float) * OUTF);
    cudaGetSymbolAddress(&p, g_colsq);
    cudaMemsetAsync(p, 0, sizeof(float) * OUTF);

    k_geom<<<(NE + 255) / 256, 256>>>(coord, src, dst);

    dim3 gp((NN + 127) / 128, HIDF / 128, 2);
    k_pre<<<gp, 256>>>(nf, We1);

    dim3 ge(NE / 128, HIDF / 128);
    k_e2<<<ge, 512>>>(src, dst, We1 + (size_t)2 * INF * HIDF, be1, We2, be2);
    k_c<<<NE / 64, 512>>>(dst, Wc1, bc1, Wc2);

    dim3 gn((NN + 127) / 128, HIDF / 128);
    k_n1<<<gn, 256>>>(nf, Wn1, bn1);
    k_n2<<<(NN + 127) / 128, 256>>>(Wn2, bn2, out);

    k_xout<<<(NN + 255) / 256, 256>>>(coord, out);
    k_bn<<<(NN * OUTF + 255) / 256, 256>>>(gamma, beta, out);
}

// round 6
// speedup vs baseline: 2.7902x; 1.1217x over previous
#include <cuda_runtime.h>
#include <math.h>
#include <stdint.h>

#define NN 50000
#define NE 800000
#define INF 128
#define HIDF 256
#define OUTF 128
#define KN1 384   // IN + HID
#define TBK 16
#define TBK2 32

typedef unsigned long long u64;

__device__ __forceinline__ float silu_f(float x) {
    return x * (1.0f / (1.0f + __expf(-x)));
}

// ---- packed f32x2 helpers (sm_100+) ----
__device__ __forceinline__ u64 pk2(float lo, float hi) {
    u64 r;
    asm("mov.b64 %0, {%1, %2};" : "=l"(r) : "f"(lo), "f"(hi));
    return r;
}
__device__ __forceinline__ u64 pkb(float x) {
    u64 r;
    asm("mov.b64 %0, {%1, %1};" : "=l"(r) : "f"(x));
    return r;
}
__device__ __forceinline__ void upk2(u64 v, float& lo, float& hi) {
    asm("mov.b64 {%0, %1}, %2;" : "=f"(lo), "=f"(hi) : "l"(v));
}
__device__ __forceinline__ void fma2(u64& acc, u64 a, u64 b) {
    asm("fma.rn.f32x2 %0, %1, %2, %0;" : "+l"(acc) : "l"(a), "l"(b));
}

__device__ __forceinline__ void mt_step(u64 (&acc2)[8][4], const float* __restrict__ Arow,
                                        const float* __restrict__ Brow, int ty8, int tx8) {
    float4 a0 = *(const float4*)(Arow + ty8);
    float4 a1 = *(const float4*)(Arow + ty8 + 4);
    float4 b0 = *(const float4*)(Brow + tx8);
    float4 b1 = *(const float4*)(Brow + tx8 + 4);
    float ar[8] = {a0.x, a0.y, a0.z, a0.w, a1.x, a1.y, a1.z, a1.w};
    u64 br2[4] = {pk2(b0.x, b0.y), pk2(b0.z, b0.w), pk2(b1.x, b1.y), pk2(b1.z, b1.w)};
#pragma unroll
    for (int i = 0; i < 8; i++) {
        u64 aa = pkb(ar[i]);
#pragma unroll
        for (int jp = 0; jp < 4; jp++) fma2(acc2[i][jp], aa, br2[jp]);
    }
}

// ---- tf32 mma helpers ----
__device__ __forceinline__ uint32_t f2tf(float x) {
    uint32_t r;
    asm("cvt.rna.tf32.f32 %0, %1;" : "=r"(r) : "f"(x));
    return r;
}
__device__ __forceinline__ void mma_tf32(float (&c)[4], const uint32_t (&a)[4],
                                         const uint32_t (&b)[2]) {
    asm("mma.sync.aligned.m16n8k8.row.col.f32.tf32.tf32.f32 "
        "{%0,%1,%2,%3}, {%4,%5,%6,%7}, {%8,%9}, {%0,%1,%2,%3};"
        : "+f"(c[0]), "+f"(c[1]), "+f"(c[2]), "+f"(c[3])
        : "r"(a[0]), "r"(a[1]), "r"(a[2]), "r"(a[3]), "r"(b[0]), "r"(b[1]));
}

__device__ __forceinline__ void red_v2(float* p, float a, float b) {
    asm volatile("red.global.add.v2.f32 [%0], {%1, %2};"
                 :: "l"(p), "f"(a), "f"(b) : "memory");
}

__device__ __forceinline__ void cp16(uint32_t s_addr, const void* g) {
    asm volatile("cp.async.cg.shared.global [%0], [%1], 16;" :: "r"(s_addr), "l"(g));
}
__device__ __forceinline__ void cp_commit_wait() {
    asm volatile("cp.async.commit_group;");
    asm volatile("cp.async.wait_group 0;");
}

// ---------------- scratch ----------------
__device__ float g_xdiff[NE * 4];
__device__ float g_pa[(size_t)NN * HIDF];
__device__ float g_pb[(size_t)NN * HIDF];
__device__ uint32_t g_msgh[(size_t)NE * HIDF];   // tf32 bits
__device__ float g_hneigh[(size_t)NN * HIDF];
__device__ float g_xsum[NN * 3];
__device__ float g_deg[NN];
__device__ float g_hn1[(size_t)NN * HIDF];
__device__ float g_colsum[OUTF];
__device__ float g_colsq[OUTF];
__device__ uint32_t g_wt_e2[HIDF * HIDF];        // tf32 of W_e2
__device__ uint32_t g_wt_c1[HIDF * HIDF];        // tf32 of W_c1

// ---------------- weight tf32 pre-convert ----------------
__global__ void k_cvtw(const float* __restrict__ We2, const float* __restrict__ Wc1) {
    int i = blockIdx.x * blockDim.x + threadIdx.x;
    if (i >= HIDF * HIDF) return;
    g_wt_e2[i] = f2tf(We2[i]);
    g_wt_c1[i] = f2tf(Wc1[i]);
}

// ---------------- edge geometry ----------------
__global__ void k_geom(const float* __restrict__ coord,
                       const int* __restrict__ src,
                       const int* __restrict__ dst) {
    int e = blockIdx.x * blockDim.x + threadIdx.x;
    if (e >= NE) return;
    int s = src[e], d = dst[e];
    float ax = coord[s * 3 + 0], ay = coord[s * 3 + 1], az = coord[s * 3 + 2];
    float bx = coord[d * 3 + 0], by = coord[d * 3 + 1], bz = coord[d * 3 + 2];
    float dx = ax - bx, dy = ay - by, dz = az - bz;
    float r = dx * dx + dy * dy + dz * dz;
    float inv = 1.0f / (sqrtf(r) + 1e-30f);
    ((float4*)g_xdiff)[e] = make_float4(dx * inv, dy * inv, dz * inv, r);
    atomicAdd(&g_deg[d], 1.0f);
}

// ---------------- node pre-GEMM: P_a = nf@W_a, P_b = nf@W_b (fp32) ----------------
__global__ __launch_bounds__(256, 2)
void k_pre(const float* __restrict__ nf, const float* __restrict__ W) {
    __shared__ float As[TBK][128 + 4];
    __shared__ float Bs[TBK][128 + 4];
    const int tid = threadIdx.x;
    const int row0 = blockIdx.x * 128;
    const int col0 = blockIdx.y * 128;
    const float* Wz = W + (size_t)blockIdx.z * INF * HIDF;
    float* out = blockIdx.z ? g_pb : g_pa;
    const int tx = tid & 15;
    const int ty = tid >> 4;
    u64 acc2[8][4];
#pragma unroll
    for (int i = 0; i < 8; i++)
#pragma unroll
        for (int j = 0; j < 4; j++) acc2[i][j] = 0ull;

    for (int kt = 0; kt < INF / TBK; kt++) {
#pragma unroll
        for (int i = 0; i < 2; i++) {
            int f = tid + i * 256;
            int r = f >> 2;
            int kk = (f & 3) << 2;
            int rr = min(row0 + r, NN - 1);
            float4 v = *(const float4*)(nf + (size_t)rr * INF + kt * TBK + kk);
            As[kk + 0][r] = v.x; As[kk + 1][r] = v.y;
            As[kk + 2][r] = v.z; As[kk + 3][r] = v.w;
        }
#pragma unroll
        for (int i = 0; i < 2; i++) {
            int f = tid + i * 256;
            int kk = f >> 5;
            int c = (f & 31) << 2;
            *(float4*)&Bs[kk][c] =
                *(const float4*)(Wz + (size_t)(kt * TBK + kk) * HIDF + col0 + c);
        }
        __syncthreads();
#pragma unroll
        for (int k = 0; k < TBK; k++)
            mt_step(acc2, &As[k][0], &Bs[k][0], ty * 8, tx * 8);
        __syncthreads();
    }
#pragma unroll
    for (int i = 0; i < 8; i++) {
        int row = row0 + ty * 8 + i;
        if (row < NN) {
            float a[8];
#pragma unroll
            for (int jp = 0; jp < 4; jp++) upk2(acc2[i][jp], a[2 * jp], a[2 * jp + 1]);
            *(float4*)(out + (size_t)row * HIDF + col0 + tx * 8) =
                make_float4(a[0], a[1], a[2], a[3]);
            *(float4*)(out + (size_t)row * HIDF + col0 + tx * 8 + 4) =
                make_float4(a[4], a[5], a[6], a[7]);
        }
    }
}

// ---------------- fused edge GEMM2 (tf32, 512 thr, TBK2=32, cp.async B) ----------------
__global__ __launch_bounds__(512, 2)
void k_e2(const int* __restrict__ src, const int* __restrict__ dst,
          const float* __restrict__ W1row, const float* __restrict__ b1,
          const float* __restrict__ b2) {
    __shared__ uint32_t As[128][36];        // pad 36: (4g+tig) mod 32 unique
    __shared__ uint32_t Bs[TBK2][128 + 8];  // stride 136
    __shared__ int s_src[128];
    __shared__ int s_dst[128];
    __shared__ float s_rad[128];
    __shared__ float s_wr[HIDF];
    __shared__ float s_b1[HIDF];
    __shared__ float s_b2[128];
    const int tid = threadIdx.x;
    const int row0 = blockIdx.x * 128;
    const int col0 = blockIdx.y * 128;
    if (tid < 128) {
        int e = row0 + tid;
        s_src[tid] = src[e];
        s_dst[tid] = dst[e];
        s_rad[tid] = g_xdiff[e * 4 + 3];
        s_b2[tid] = b2[col0 + tid];
    }
    if (tid < HIDF) {
        s_wr[tid] = W1row[tid];
        s_b1[tid] = b1[tid];
    }
    __syncthreads();
    const uint32_t bs_base = (uint32_t)__cvta_generic_to_shared(&Bs[0][0]);
    const int lane = tid & 31;
    const int g = lane >> 2;
    const int tig = lane & 3;
    const int wid = tid >> 5;
    const int wr = wid >> 2;
    const int wc = wid & 3;
    float c[2][4][4];
#pragma unroll
    for (int mt = 0; mt < 2; mt++)
#pragma unroll
        for (int nt = 0; nt < 4; nt++)
#pragma unroll
            for (int q = 0; q < 4; q++) c[mt][nt][q] = 0.0f;

    for (int kt = 0; kt < HIDF / TBK2; kt++) {  // 8
        // B staging: 32x128 words = 1024 uint4, 2/thread via cp.async
#pragma unroll
        for (int i = 0; i < 2; i++) {
            int f = tid + i * 512;
            int kk = f >> 5;
            int cc = (f & 31) << 2;
            cp16(bs_base + (uint32_t)(kk * 136 + cc) * 4,
                 g_wt_e2 + (size_t)(kt * TBK2 + kk) * HIDF + col0 + cc);
        }
        // A staging: 128x32 words = 1024 uint4, 2/thread (gather+silu+cvt)
#pragma unroll
        for (int i = 0; i < 2; i++) {
            int f = tid + i * 512;
            int r = f >> 3;
            int kk = (f & 7) << 2;
            int kg = kt * TBK2 + kk;
            float4 va = *(const float4*)(g_pa + (size_t)s_src[r] * HIDF + kg);
            float4 vb = *(const float4*)(g_pb + (size_t)s_dst[r] * HIDF + kg);
            float rad = s_rad[r];
            uint4 o;
            o.x = f2tf(silu_f(va.x + vb.x + rad * s_wr[kg + 0] + s_b1[kg + 0]));
            o.y = f2tf(silu_f(va.y + vb.y + rad * s_wr[kg + 1] + s_b1[kg + 1]));
            o.z = f2tf(silu_f(va.z + vb.z + rad * s_wr[kg + 2] + s_b1[kg + 2]));
            o.w = f2tf(silu_f(va.w + vb.w + rad * s_wr[kg + 3] + s_b1[kg + 3]));
            *(uint4*)&As[r][kk] = o;
        }
        cp_commit_wait();
        __syncthreads();
#pragma unroll
        for (int ks = 0; ks < TBK2; ks += 8) {
            uint32_t af[2][4], bf[4][2];
#pragma unroll
            for (int mt = 0; mt < 2; mt++) {
                int rb = wr * 32 + mt * 16;
                af[mt][0] = As[rb + g][ks + tig];
                af[mt][1] = As[rb + g + 8][ks + tig];
                af[mt][2] = As[rb + g][ks + tig + 4];
                af[mt][3] = As[rb + g + 8][ks + tig + 4];
            }
#pragma unroll
            for (int nt = 0; nt < 4; nt++) {
                int cb = wc * 32 + nt * 8;
                bf[nt][0] = Bs[ks + tig][cb + g];
                bf[nt][1] = Bs[ks + tig + 4][cb + g];
            }
#pragma unroll
            for (int mt = 0; mt < 2; mt++)
#pragma unroll
                for (int nt = 0; nt < 4; nt++)
                    mma_tf32(c[mt][nt], af[mt], bf[nt]);
        }
        __syncthreads();
    }
    // epilogue: bias+silu, store tf32 msg_h, reduce h_neigh
#pragma unroll
    for (int mt = 0; mt < 2; mt++) {
        int r1 = wr * 32 + mt * 16 + g;
        int r2 = r1 + 8;
        int e1 = row0 + r1, e2 = row0 + r2;
        int d1 = s_dst[r1], d2 = s_dst[r2];
#pragma unroll
        for (int nt = 0; nt < 4; nt++) {
            int lc = wc * 32 + nt * 8 + tig * 2;
            float v0 = silu_f(c[mt][nt][0] + s_b2[lc]);
            float v1 = silu_f(c[mt][nt][1] + s_b2[lc + 1]);
            float v2 = silu_f(c[mt][nt][2] + s_b2[lc]);
            float v3 = silu_f(c[mt][nt][3] + s_b2[lc + 1]);
            *(uint2*)(g_msgh + (size_t)e1 * HIDF + col0 + lc) =
                make_uint2(f2tf(v0), f2tf(v1));
            *(uint2*)(g_msgh + (size_t)e2 * HIDF + col0 + lc) =
                make_uint2(f2tf(v2), f2tf(v3));
            red_v2(g_hneigh + (size_t)d1 * HIDF + col0 + lc, v0, v1);
            red_v2(g_hneigh + (size_t)d2 * HIDF + col0 + lc, v2, v3);
        }
    }
}

// ---------------- coord GEMM (tf32, 512 thr, TBK2=32, pure-copy staging) ----------------
__global__ __launch_bounds__(512, 2)
void k_c(const int* __restrict__ dst, const float* __restrict__ b,
         const float* __restrict__ Wc2) {
    __shared__ uint32_t As[64][36];
    __shared__ uint32_t Bs[TBK2][256 + 8];   // stride 264
    __shared__ float s_w2[256];
    __shared__ float s_b1[256];
    __shared__ float red[64];
    __shared__ int s_dst[64];
    const int tid = threadIdx.x;
    const int row0 = blockIdx.x * 64;
    if (tid < 256) {
        s_w2[tid] = Wc2[tid];
        s_b1[tid] = b[tid];
    }
    if (tid < 64) {
        s_dst[tid] = dst[row0 + tid];
        red[tid] = 0.0f;
    }
    __syncthreads();
    const uint32_t bs_base = (uint32_t)__cvta_generic_to_shared(&Bs[0][0]);
    const int lane = tid & 31;
    const int g = lane >> 2;
    const int tig = lane & 3;
    const int wid = tid >> 5;
    const int wr = wid >> 3;
    const int wc = wid & 7;
    float c[2][4][4];
#pragma unroll
    for (int mt = 0; mt < 2; mt++)
#pragma unroll
        for (int nt = 0; nt < 4; nt++)
#pragma unroll
            for (int q = 0; q < 4; q++) c[mt][nt][q] = 0.0f;

    for (int kt = 0; kt < HIDF / TBK2; kt++) {  // 8
        // B staging: 32x256 = 2048 uint4, 4/thread via cp.async
#pragma unroll
        for (int i = 0; i < 4; i++) {
            int f = tid + i * 512;
            int kk = f >> 6;
            int cc = (f & 63) << 2;
            cp16(bs_base + (uint32_t)(kk * 264 + cc) * 4,
                 g_wt_c1 + (size_t)(kt * TBK2 + kk) * HIDF + cc);
        }
        // A staging: 64x32 = 512 uint4, 1/thread, pure copy (msg_h already tf32)
        {
            int r = tid >> 3;
            int kk = (tid & 7) << 2;
            *(uint4*)&As[r][kk] =
                *(const uint4*)(g_msgh + (size_t)(row0 + r) * HIDF + kt * TBK2 + kk);
        }
        cp_commit_wait();
        __syncthreads();
#pragma unroll
        for (int ks = 0; ks < TBK2; ks += 8) {
            uint32_t af[2][4], bf[4][2];
#pragma unroll
            for (int mt = 0; mt < 2; mt++) {
                int rb = wr * 32 + mt * 16;
                af[mt][0] = As[rb + g][ks + tig];
                af[mt][1] = As[rb + g + 8][ks + tig];
                af[mt][2] = As[rb + g][ks + tig + 4];
                af[mt][3] = As[rb + g + 8][ks + tig + 4];
            }
#pragma unroll
            for (int nt = 0; nt < 4; nt++) {
                int cb = wc * 32 + nt * 8;
                bf[nt][0] = Bs[ks + tig][cb + g];
                bf[nt][1] = Bs[ks + tig + 4][cb + g];
            }
#pragma unroll
            for (int mt = 0; mt < 2; mt++)
#pragma unroll
                for (int nt = 0; nt < 4; nt++)
                    mma_tf32(c[mt][nt], af[mt], bf[nt]);
        }
        __syncthreads();
    }
    // epilogue: silu + dot with w2, per-row reduce, scatter
#pragma unroll
    for (int mt = 0; mt < 2; mt++) {
        float s1 = 0.0f, s2 = 0.0f;
#pragma unroll
        for (int nt = 0; nt < 4; nt++) {
            int lc = wc * 32 + nt * 8 + tig * 2;
            s1 += silu_f(c[mt][nt][0] + s_b1[lc]) * s_w2[lc]
                + silu_f(c[mt][nt][1] + s_b1[lc + 1]) * s_w2[lc + 1];
            s2 += silu_f(c[mt][nt][2] + s_b1[lc]) * s_w2[lc]
                + silu_f(c[mt][nt][3] + s_b1[lc + 1]) * s_w2[lc + 1];
        }
        s1 += __shfl_xor_sync(0xffffffffu, s1, 1);
        s1 += __shfl_xor_sync(0xffffffffu, s1, 2);
        s2 += __shfl_xor_sync(0xffffffffu, s2, 1);
        s2 += __shfl_xor_sync(0xffffffffu, s2, 2);
        if (tig == 0) {
            atomicAdd(&red[wr * 32 + mt * 16 + g], s1);
            atomicAdd(&red[wr * 32 + mt * 16 + g + 8], s2);
        }
    }
    __syncthreads();
    if (tid < 64) {
        int e = row0 + tid;
        float s = red[tid];
        float4 xd = *(const float4*)(g_xdiff + (size_t)e * 4);
        int d = s_dst[tid];
        atomicAdd(&g_xsum[d * 3 + 0], s * xd.x);
        atomicAdd(&g_xsum[d * 3 + 1], s * xd.y);
        atomicAdd(&g_xsum[d * 3 + 2], s * xd.z);
    }
}

// ---------------- node GEMM 1 (fp32) ----------------
__global__ __launch_bounds__(256, 2)
void k_n1(const float* __restrict__ nf, const float* __restrict__ W,
          const float* __restrict__ b) {
    __shared__ float As[TBK][128 + 4];
    __shared__ float Bs[TBK][128 + 4];
    const int tid = threadIdx.x;
    const int row0 = blockIdx.x * 128;
    const int col0 = blockIdx.y * 128;
    const int tx = tid & 15;
    const int ty = tid >> 4;
    u64 acc2[8][4];
#pragma unroll
    for (int i = 0; i < 8; i++)
#pragma unroll
        for (int j = 0; j < 4; j++) acc2[i][j] = 0ull;

    for (int kt = 0; kt < KN1 / TBK; kt++) {
#pragma unroll
        for (int i = 0; i < 2; i++) {
            int f = tid + i * 256;
            int r = f >> 2;
            int kk = (f & 3) << 2;
            int kg = kt * TBK + kk;
            int rr = min(row0 + r, NN - 1);
            float4 v;
            if (kg < INF)
                v = *(const float4*)(nf + (size_t)rr * INF + kg);
            else
                v = *(const float4*)(g_hneigh + (size_t)rr * HIDF + (kg - INF));
            As[kk + 0][r] = v.x; As[kk + 1][r] = v.y;
            As[kk + 2][r] = v.z; As[kk + 3][r] = v.w;
        }
#pragma unroll
        for (int i = 0; i < 2; i++) {
            int f = tid + i * 256;
            int kk = f >> 5;
            int c = (f & 31) << 2;
            *(float4*)&Bs[kk][c] =
                *(const float4*)(W + (size_t)(kt * TBK + kk) * HIDF + col0 + c);
        }
        __syncthreads();
#pragma unroll
        for (int k = 0; k < TBK; k++)
            mt_step(acc2, &As[k][0], &Bs[k][0], ty * 8, tx * 8);
        __syncthreads();
    }
    float bb[8];
#pragma unroll
    for (int j = 0; j < 8; j++) bb[j] = b[col0 + tx * 8 + j];
#pragma unroll
    for (int i = 0; i < 8; i++) {
        int row = row0 + ty * 8 + i;
        if (row < NN) {
            float a[8];
#pragma unroll
            for (int jp = 0; jp < 4; jp++) upk2(acc2[i][jp], a[2 * jp], a[2 * jp + 1]);
            float4 o0, o1;
            o0.x = silu_f(a[0] + bb[0]); o0.y = silu_f(a[1] + bb[1]);
            o0.z = silu_f(a[2] + bb[2]); o0.w = silu_f(a[3] + bb[3]);
            o1.x = silu_f(a[4] + bb[4]); o1.y = silu_f(a[5] + bb[5]);
            o1.z = silu_f(a[6] + bb[6]); o1.w = silu_f(a[7] + bb[7]);
            *(float4*)(g_hn1 + (size_t)row * HIDF + col0 + tx * 8) = o0;
            *(float4*)(g_hn1 + (size_t)row * HIDF + col0 + tx * 8 + 4) = o1;
        }
    }
}

// ---------------- node GEMM 2 + BN stats (fp32) ----------------
__global__ __launch_bounds__(256, 2)
void k_n2(const float* __restrict__ W, const float* __restrict__ b,
          float* __restrict__ out) {
    __shared__ float As[TBK][128 + 4];
    __shared__ float Bs[TBK][128 + 4];
    __shared__ float csum[128];
    __shared__ float csq[128];
    const int tid = threadIdx.x;
    const int row0 = blockIdx.x * 128;
    if (tid < 128) { csum[tid] = 0.0f; csq[tid] = 0.0f; }
    const int tx = tid & 15;
    const int ty = tid >> 4;
    u64 acc2[8][4];
#pragma unroll
    for (int i = 0; i < 8; i++)
#pragma unroll
        for (int j = 0; j < 4; j++) acc2[i][j] = 0ull;

    for (int kt = 0; kt < HIDF / TBK; kt++) {
#pragma unroll
        for (int i = 0; i < 2; i++) {
            int f = tid + i * 256;
            int r = f >> 2;
            int kk = (f & 3) << 2;
            int rr = min(row0 + r, NN - 1);
            float4 v = *(const float4*)(g_hn1 + (size_t)rr * HIDF + kt * TBK + kk);
            As[kk + 0][r] = v.x; As[kk + 1][r] = v.y;
            As[kk + 2][r] = v.z; As[kk + 3][r] = v.w;
        }
#pragma unroll
        for (int i = 0; i < 2; i++) {
            int f = tid + i * 256;
            int kk = f >> 5;
            int c = (f & 31) << 2;
            *(float4*)&Bs[kk][c] =
                *(const float4*)(W + (size_t)(kt * TBK + kk) * OUTF + c);
        }
        __syncthreads();
#pragma unroll
        for (int k = 0; k < TBK; k++)
            mt_step(acc2, &As[k][0], &Bs[k][0], ty * 8, tx * 8);
        __syncthreads();
    }
    float bb[8];
#pragma unroll
    for (int j = 0; j < 8; j++) bb[j] = b[tx * 8 + j];
    float cs[8], cq[8];
#pragma unroll
    for (int j = 0; j < 8; j++) { cs[j] = 0.0f; cq[j] = 0.0f; }
#pragma unroll
    for (int i = 0; i < 8; i++) {
        int row = row0 + ty * 8 + i;
        if (row < NN) {
            float a[8], h[8];
#pragma unroll
            for (int jp = 0; jp < 4; jp++) upk2(acc2[i][jp], a[2 * jp], a[2 * jp + 1]);
#pragma unroll
            for (int j = 0; j < 8; j++) {
                h[j] = a[j] + bb[j];
                cs[j] += h[j];
                cq[j] += h[j] * h[j];
            }
            *(float4*)(out + (size_t)row * OUTF + tx * 8) =
                make_float4(h[0], h[1], h[2], h[3]);
            *(float4*)(out + (size_t)row * OUTF + tx * 8 + 4) =
                make_float4(h[4], h[5], h[6], h[7]);
        }
    }
#pragma unroll
    for (int j = 0; j < 8; j++) {
        atomicAdd(&csum[tx * 8 + j], cs[j]);
        atomicAdd(&csq[tx * 8 + j], cq[j]);
    }
    __syncthreads();
    if (tid < 128) {
        atomicAdd(&g_colsum[tid], csum[tid]);
        atomicAdd(&g_colsq[tid], csq[tid]);
    }
}

// ---------------- x output ----------------
__global__ void k_xout(const float* __restrict__ coord, float* __restrict__ out) {
    int n = blockIdx.x * blockDim.x + threadIdx.x;
    if (n >= NN) return;
    float inv = 1.0f / fmaxf(g_deg[n], 1.0f);
    float* o = out + (size_t)NN * OUTF + n * 3;
    o[0] = coord[n * 3 + 0] + g_xsum[n * 3 + 0] * inv;
    o[1] = coord[n * 3 + 1] + g_xsum[n * 3 + 1] * inv;
    o[2] = coord[n * 3 + 2] + g_xsum[n * 3 + 2] * inv;
}

// ---------------- BatchNorm finalize ----------------
__global__ void k_bn(const float* __restrict__ gamma, const float* __restrict__ beta,
                     float* __restrict__ out) {
    int idx = blockIdx.x * blockDim.x + threadIdx.x;
    if (idx >= NN * OUTF) return;
    int c = idx & (OUTF - 1);
    const float invN = 1.0f / (float)NN;
    float mu = g_colsum[c] * invN;
    float var = g_colsq[c] * invN - mu * mu;
    float h = out[idx];
    out[idx] = (h - mu) * rsqrtf(var + 1e-5f) * gamma[c] + beta[c];
}

// ---------------- launch ----------------
extern "C" void kernel_launch(void* const* d_in, const int* in_sizes, int n_in,
                              void* d_out, int out_size) {
    const float* nf    = (const float*)d_in[0];
    const float* coord = (const float*)d_in[1];
    const int*   src   = (const int*)d_in[2];
    const int*   dst   = (const int*)d_in[3];
    const float* We1   = (const float*)d_in[4];
    const float* be1   = (const float*)d_in[5];
    const float* We2   = (const float*)d_in[6];
    const float* be2   = (const float*)d_in[7];
    const float* Wc1   = (const float*)d_in[8];
    const float* bc1   = (const float*)d_in[9];
    const float* Wc2   = (const float*)d_in[10];
    const float* Wn1   = (const float*)d_in[11];
    const float* bn1   = (const float*)d_in[12];
    const float* Wn2   = (const float*)d_in[13];
    const float* bn2   = (const float*)d_in[14];
    const float* gamma = (const float*)d_in[15];
    const float* beta  = (const float*)d_in[16];
    float* out = (float*)d_out;

    void* p;
    cudaGetSymbolAddress(&p, g_hneigh);
    cudaMemsetAsync(p, 0, sizeof(float) * (size_t)NN * HIDF);
    cudaGetSymbolAddress(&p, g_xsum);
    cudaMemsetAsync(p, 0, sizeof(float) * NN * 3);
    cudaGetSymbolAddress(&p, g_deg);
    cudaMemsetAsync(p, 0, sizeof(float) * NN);
    cudaGetSymbolAddress(&p, g_colsum);
    cudaMemsetAsync(p, 0, sizeof(float) * OUTF);
    cudaGetSymbolAddress(&p, g_colsq);
    cudaMemsetAsync(p, 0, sizeof(float) * OUTF);

    k_cvtw<<<(HIDF * HIDF + 255) / 256, 256>>>(We2, Wc1);
    k_geom<<<(NE + 255) / 256, 256>>>(coord, src, dst);

    dim3 gp((NN + 127) / 128, HIDF / 128, 2);
    k_pre<<<gp, 256>>>(nf, We1);

    dim3 ge(NE / 128, HIDF / 128);
    k_e2<<<ge, 512>>>(src, dst, We1 + (size_t)2 * INF * HIDF, be1, be2);
    k_c<<<NE / 64, 512>>>(dst, bc1, Wc2);

    dim3 gn((NN + 127) / 128, HIDF / 128);
    k_n1<<<gn, 256>>>(nf, Wn1, bn1);
    k_n2<<<(NN + 127) / 128, 256>>>(Wn2, bn2, out);

    k_xout<<<(NN + 255) / 256, 256>>>(coord, out);
    k_bn<<<(NN * OUTF + 255) / 256, 256>>>(gamma, beta, out);
}

// round 7
// speedup vs baseline: 3.1660x; 1.1347x over previous
#include <cuda_runtime.h>
#include <math.h>
#include <stdint.h>

#define NN 50000
#define NE 800000
#define INF 128
#define HIDF 256
#define OUTF 128
#define KN1 384   // IN + HID
#define TBK 16
#define TBK2 32

typedef unsigned long long u64;

__device__ __forceinline__ float silu_f(float x) {
    return x * (1.0f / (1.0f + __expf(-x)));
}

// ---- packed f32x2 helpers (sm_100+) ----
__device__ __forceinline__ u64 pk2(float lo, float hi) {
    u64 r;
    asm("mov.b64 %0, {%1, %2};" : "=l"(r) : "f"(lo), "f"(hi));
    return r;
}
__device__ __forceinline__ u64 pkb(float x) {
    u64 r;
    asm("mov.b64 %0, {%1, %1};" : "=l"(r) : "f"(x));
    return r;
}
__device__ __forceinline__ void upk2(u64 v, float& lo, float& hi) {
    asm("mov.b64 {%0, %1}, %2;" : "=f"(lo), "=f"(hi) : "l"(v));
}
__device__ __forceinline__ void fma2(u64& acc, u64 a, u64 b) {
    asm("fma.rn.f32x2 %0, %1, %2, %0;" : "+l"(acc) : "l"(a), "l"(b));
}

__device__ __forceinline__ void mt_step(u64 (&acc2)[8][4], const float* __restrict__ Arow,
                                        const float* __restrict__ Brow, int ty8, int tx8) {
    float4 a0 = *(const float4*)(Arow + ty8);
    float4 a1 = *(const float4*)(Arow + ty8 + 4);
    float4 b0 = *(const float4*)(Brow + tx8);
    float4 b1 = *(const float4*)(Brow + tx8 + 4);
    float ar[8] = {a0.x, a0.y, a0.z, a0.w, a1.x, a1.y, a1.z, a1.w};
    u64 br2[4] = {pk2(b0.x, b0.y), pk2(b0.z, b0.w), pk2(b1.x, b1.y), pk2(b1.z, b1.w)};
#pragma unroll
    for (int i = 0; i < 8; i++) {
        u64 aa = pkb(ar[i]);
#pragma unroll
        for (int jp = 0; jp < 4; jp++) fma2(acc2[i][jp], aa, br2[jp]);
    }
}

// ---- tf32 mma helpers ----
__device__ __forceinline__ uint32_t f2tf(float x) {
    uint32_t r;
    asm("cvt.rna.tf32.f32 %0, %1;" : "=r"(r) : "f"(x));
    return r;
}
__device__ __forceinline__ void mma_tf32(float (&c)[4], const uint32_t (&a)[4],
                                         const uint32_t (&b)[2]) {
    asm("mma.sync.aligned.m16n8k8.row.col.f32.tf32.tf32.f32 "
        "{%0,%1,%2,%3}, {%4,%5,%6,%7}, {%8,%9}, {%0,%1,%2,%3};"
        : "+f"(c[0]), "+f"(c[1]), "+f"(c[2]), "+f"(c[3])
        : "r"(a[0]), "r"(a[1]), "r"(a[2]), "r"(a[3]), "r"(b[0]), "r"(b[1]));
}

__device__ __forceinline__ void red_v2(float* p, float a, float b) {
    asm volatile("red.global.add.v2.f32 [%0], {%1, %2};"
                 :: "l"(p), "f"(a), "f"(b) : "memory");
}

__device__ __forceinline__ void cp16(uint32_t s_addr, const void* g) {
    asm volatile("cp.async.cg.shared.global [%0], [%1], 16;" :: "r"(s_addr), "l"(g));
}
__device__ __forceinline__ void cp_commit_wait() {
    asm volatile("cp.async.commit_group;");
    asm volatile("cp.async.wait_group 0;");
}

// ---------------- scratch ----------------
__device__ float g_xdiff[NE * 4];
__device__ float g_pa[(size_t)NN * HIDF];
__device__ float g_pb[(size_t)NN * HIDF];
__device__ uint32_t g_msgh[(size_t)NE * HIDF];   // tf32 bits
__device__ float g_hneigh[(size_t)NN * HIDF];
__device__ float g_xsum[NN * 3];
__device__ float g_deg[NN];
__device__ float g_hn1[(size_t)NN * HIDF];
__device__ float g_colsum[OUTF];
__device__ float g_colsq[OUTF];
__device__ uint32_t g_wt_e2[HIDF * HIDF];        // tf32 of W_e2
__device__ uint32_t g_wt_c1[HIDF * HIDF];        // tf32 of W_c1

// ---------------- weight tf32 pre-convert ----------------
__global__ void k_cvtw(const float* __restrict__ We2, const float* __restrict__ Wc1) {
    int i = blockIdx.x * blockDim.x + threadIdx.x;
    if (i >= HIDF * HIDF) return;
    g_wt_e2[i] = f2tf(We2[i]);
    g_wt_c1[i] = f2tf(Wc1[i]);
}

// ---------------- edge geometry ----------------
__global__ void k_geom(const float* __restrict__ coord,
                       const int* __restrict__ src,
                       const int* __restrict__ dst) {
    int e = blockIdx.x * blockDim.x + threadIdx.x;
    if (e >= NE) return;
    int s = src[e], d = dst[e];
    float ax = coord[s * 3 + 0], ay = coord[s * 3 + 1], az = coord[s * 3 + 2];
    float bx = coord[d * 3 + 0], by = coord[d * 3 + 1], bz = coord[d * 3 + 2];
    float dx = ax - bx, dy = ay - by, dz = az - bz;
    float r = dx * dx + dy * dy + dz * dz;
    float inv = 1.0f / (sqrtf(r) + 1e-30f);
    ((float4*)g_xdiff)[e] = make_float4(dx * inv, dy * inv, dz * inv, r);
    atomicAdd(&g_deg[d], 1.0f);
}

// ---------------- node pre-GEMM: P_a = nf@W_a, P_b = nf@W_b (fp32) ----------------
__global__ __launch_bounds__(256, 2)
void k_pre(const float* __restrict__ nf, const float* __restrict__ W) {
    __shared__ float As[TBK][128 + 4];
    __shared__ float Bs[TBK][128 + 4];
    const int tid = threadIdx.x;
    const int row0 = blockIdx.x * 128;
    const int col0 = blockIdx.y * 128;
    const float* Wz = W + (size_t)blockIdx.z * INF * HIDF;
    float* out = blockIdx.z ? g_pb : g_pa;
    const int tx = tid & 15;
    const int ty = tid >> 4;
    u64 acc2[8][4];
#pragma unroll
    for (int i = 0; i < 8; i++)
#pragma unroll
        for (int j = 0; j < 4; j++) acc2[i][j] = 0ull;

    for (int kt = 0; kt < INF / TBK; kt++) {
#pragma unroll
        for (int i = 0; i < 2; i++) {
            int f = tid + i * 256;
            int r = f >> 2;
            int kk = (f & 3) << 2;
            int rr = min(row0 + r, NN - 1);
            float4 v = *(const float4*)(nf + (size_t)rr * INF + kt * TBK + kk);
            As[kk + 0][r] = v.x; As[kk + 1][r] = v.y;
            As[kk + 2][r] = v.z; As[kk + 3][r] = v.w;
        }
#pragma unroll
        for (int i = 0; i < 2; i++) {
            int f = tid + i * 256;
            int kk = f >> 5;
            int c = (f & 31) << 2;
            *(float4*)&Bs[kk][c] =
                *(const float4*)(Wz + (size_t)(kt * TBK + kk) * HIDF + col0 + c);
        }
        __syncthreads();
#pragma unroll
        for (int k = 0; k < TBK; k++)
            mt_step(acc2, &As[k][0], &Bs[k][0], ty * 8, tx * 8);
        __syncthreads();
    }
#pragma unroll
    for (int i = 0; i < 8; i++) {
        int row = row0 + ty * 8 + i;
        if (row < NN) {
            float a[8];
#pragma unroll
            for (int jp = 0; jp < 4; jp++) upk2(acc2[i][jp], a[2 * jp], a[2 * jp + 1]);
            *(float4*)(out + (size_t)row * HIDF + col0 + tx * 8) =
                make_float4(a[0], a[1], a[2], a[3]);
            *(float4*)(out + (size_t)row * HIDF + col0 + tx * 8 + 4) =
                make_float4(a[4], a[5], a[6], a[7]);
        }
    }
}

// ---------------- fused edge GEMM2 (tf32, 64x256 tile: gather A staged ONCE) ----------------
__global__ __launch_bounds__(512, 2)
void k_e2(const int* __restrict__ src, const int* __restrict__ dst,
          const float* __restrict__ W1row, const float* __restrict__ b1,
          const float* __restrict__ b2) {
    __shared__ uint32_t As[64][36];         // pad 36: conflict-free frags
    __shared__ uint32_t Bs[TBK2][256 + 8];  // stride 264
    __shared__ int s_src[64];
    __shared__ int s_dst[64];
    __shared__ float s_rad[64];
    __shared__ float s_wr[HIDF];
    __shared__ float s_b1[HIDF];
    __shared__ float s_b2[HIDF];
    const int tid = threadIdx.x;
    const int row0 = blockIdx.x * 64;
    if (tid < 64) {
        int e = row0 + tid;
        s_src[tid] = src[e];
        s_dst[tid] = dst[e];
        s_rad[tid] = g_xdiff[e * 4 + 3];
    }
    if (tid < HIDF) {
        s_wr[tid] = W1row[tid];
        s_b1[tid] = b1[tid];
        s_b2[tid] = b2[tid];
    }
    __syncthreads();
    const uint32_t bs_base = (uint32_t)__cvta_generic_to_shared(&Bs[0][0]);
    const int lane = tid & 31;
    const int g = lane >> 2;
    const int tig = lane & 3;
    const int wid = tid >> 5;
    const int wr = wid >> 3;   // 0..1 -> 32 rows each
    const int wc = wid & 7;    // 0..7 -> 32 cols each
    float c[2][4][4];
#pragma unroll
    for (int mt = 0; mt < 2; mt++)
#pragma unroll
        for (int nt = 0; nt < 4; nt++)
#pragma unroll
            for (int q = 0; q < 4; q++) c[mt][nt][q] = 0.0f;

    for (int kt = 0; kt < HIDF / TBK2; kt++) {  // 8
        // B staging: 32x256 = 2048 uint4, 4/thread via cp.async (full 256 cols)
#pragma unroll
        for (int i = 0; i < 4; i++) {
            int f = tid + i * 512;
            int kk = f >> 6;
            int cc = (f & 63) << 2;
            cp16(bs_base + (uint32_t)(kk * 264 + cc) * 4,
                 g_wt_e2 + (size_t)(kt * TBK2 + kk) * HIDF + cc);
        }
        // A staging: 64x32 words = 512 uint4, 1/thread (gather+silu+cvt, ONCE per edge)
        {
            int r = tid >> 3;
            int kk = (tid & 7) << 2;
            int kg = kt * TBK2 + kk;
            float4 va = *(const float4*)(g_pa + (size_t)s_src[r] * HIDF + kg);
            float4 vb = *(const float4*)(g_pb + (size_t)s_dst[r] * HIDF + kg);
            float rad = s_rad[r];
            uint4 o;
            o.x = f2tf(silu_f(va.x + vb.x + rad * s_wr[kg + 0] + s_b1[kg + 0]));
            o.y = f2tf(silu_f(va.y + vb.y + rad * s_wr[kg + 1] + s_b1[kg + 1]));
            o.z = f2tf(silu_f(va.z + vb.z + rad * s_wr[kg + 2] + s_b1[kg + 2]));
            o.w = f2tf(silu_f(va.w + vb.w + rad * s_wr[kg + 3] + s_b1[kg + 3]));
            *(uint4*)&As[r][kk] = o;
        }
        cp_commit_wait();
        __syncthreads();
#pragma unroll
        for (int ks = 0; ks < TBK2; ks += 8) {
            uint32_t af[2][4], bf[4][2];
#pragma unroll
            for (int mt = 0; mt < 2; mt++) {
                int rb = wr * 32 + mt * 16;
                af[mt][0] = As[rb + g][ks + tig];
                af[mt][1] = As[rb + g + 8][ks + tig];
                af[mt][2] = As[rb + g][ks + tig + 4];
                af[mt][3] = As[rb + g + 8][ks + tig + 4];
            }
#pragma unroll
            for (int nt = 0; nt < 4; nt++) {
                int cb = wc * 32 + nt * 8;
                bf[nt][0] = Bs[ks + tig][cb + g];
                bf[nt][1] = Bs[ks + tig + 4][cb + g];
            }
#pragma unroll
            for (int mt = 0; mt < 2; mt++)
#pragma unroll
                for (int nt = 0; nt < 4; nt++)
                    mma_tf32(c[mt][nt], af[mt], bf[nt]);
        }
        __syncthreads();
    }
    // epilogue: bias+silu, store tf32 msg_h, reduce h_neigh
#pragma unroll
    for (int mt = 0; mt < 2; mt++) {
        int r1 = wr * 32 + mt * 16 + g;
        int r2 = r1 + 8;
        int e1 = row0 + r1, e2 = row0 + r2;
        int d1 = s_dst[r1], d2 = s_dst[r2];
#pragma unroll
        for (int nt = 0; nt < 4; nt++) {
            int lc = wc * 32 + nt * 8 + tig * 2;
            float v0 = silu_f(c[mt][nt][0] + s_b2[lc]);
            float v1 = silu_f(c[mt][nt][1] + s_b2[lc + 1]);
            float v2 = silu_f(c[mt][nt][2] + s_b2[lc]);
            float v3 = silu_f(c[mt][nt][3] + s_b2[lc + 1]);
            *(uint2*)(g_msgh + (size_t)e1 * HIDF + lc) = make_uint2(f2tf(v0), f2tf(v1));
            *(uint2*)(g_msgh + (size_t)e2 * HIDF + lc) = make_uint2(f2tf(v2), f2tf(v3));
            red_v2(g_hneigh + (size_t)d1 * HIDF + lc, v0, v1);
            red_v2(g_hneigh + (size_t)d2 * HIDF + lc, v2, v3);
        }
    }
}

// ---------------- coord GEMM (tf32, 512 thr, TBK2=32, pure-copy staging) ----------------
__global__ __launch_bounds__(512, 2)
void k_c(const int* __restrict__ dst, const float* __restrict__ b,
         const float* __restrict__ Wc2) {
    __shared__ uint32_t As[64][36];
    __shared__ uint32_t Bs[TBK2][256 + 8];   // stride 264
    __shared__ float s_w2[256];
    __shared__ float s_b1[256];
    __shared__ float red[64];
    __shared__ int s_dst[64];
    const int tid = threadIdx.x;
    const int row0 = blockIdx.x * 64;
    if (tid < 256) {
        s_w2[tid] = Wc2[tid];
        s_b1[tid] = b[tid];
    }
    if (tid < 64) {
        s_dst[tid] = dst[row0 + tid];
        red[tid] = 0.0f;
    }
    __syncthreads();
    const uint32_t bs_base = (uint32_t)__cvta_generic_to_shared(&Bs[0][0]);
    const int lane = tid & 31;
    const int g = lane >> 2;
    const int tig = lane & 3;
    const int wid = tid >> 5;
    const int wr = wid >> 3;
    const int wc = wid & 7;
    float c[2][4][4];
#pragma unroll
    for (int mt = 0; mt < 2; mt++)
#pragma unroll
        for (int nt = 0; nt < 4; nt++)
#pragma unroll
            for (int q = 0; q < 4; q++) c[mt][nt][q] = 0.0f;

    for (int kt = 0; kt < HIDF / TBK2; kt++) {  // 8
#pragma unroll
        for (int i = 0; i < 4; i++) {
            int f = tid + i * 512;
            int kk = f >> 6;
            int cc = (f & 63) << 2;
            cp16(bs_base + (uint32_t)(kk * 264 + cc) * 4,
                 g_wt_c1 + (size_t)(kt * TBK2 + kk) * HIDF + cc);
        }
        {
            int r = tid >> 3;
            int kk = (tid & 7) << 2;
            *(uint4*)&As[r][kk] =
                *(const uint4*)(g_msgh + (size_t)(row0 + r) * HIDF + kt * TBK2 + kk);
        }
        cp_commit_wait();
        __syncthreads();
#pragma unroll
        for (int ks = 0; ks < TBK2; ks += 8) {
            uint32_t af[2][4], bf[4][2];
#pragma unroll
            for (int mt = 0; mt < 2; mt++) {
                int rb = wr * 32 + mt * 16;
                af[mt][0] = As[rb + g][ks + tig];
                af[mt][1] = As[rb + g + 8][ks + tig];
                af[mt][2] = As[rb + g][ks + tig + 4];
                af[mt][3] = As[rb + g + 8][ks + tig + 4];
            }
#pragma unroll
            for (int nt = 0; nt < 4; nt++) {
                int cb = wc * 32 + nt * 8;
                bf[nt][0] = Bs[ks + tig][cb + g];
                bf[nt][1] = Bs[ks + tig + 4][cb + g];
            }
#pragma unroll
            for (int mt = 0; mt < 2; mt++)
#pragma unroll
                for (int nt = 0; nt < 4; nt++)
                    mma_tf32(c[mt][nt], af[mt], bf[nt]);
        }
        __syncthreads();
    }
#pragma unroll
    for (int mt = 0; mt < 2; mt++) {
        float s1 = 0.0f, s2 = 0.0f;
#pragma unroll
        for (int nt = 0; nt < 4; nt++) {
            int lc = wc * 32 + nt * 8 + tig * 2;
            s1 += silu_f(c[mt][nt][0] + s_b1[lc]) * s_w2[lc]
                + silu_f(c[mt][nt][1] + s_b1[lc + 1]) * s_w2[lc + 1];
            s2 += silu_f(c[mt][nt][2] + s_b1[lc]) * s_w2[lc]
                + silu_f(c[mt][nt][3] + s_b1[lc + 1]) * s_w2[lc + 1];
        }
        s1 += __shfl_xor_sync(0xffffffffu, s1, 1);
        s1 += __shfl_xor_sync(0xffffffffu, s1, 2);
        s2 += __shfl_xor_sync(0xffffffffu, s2, 1);
        s2 += __shfl_xor_sync(0xffffffffu, s2, 2);
        if (tig == 0) {
            atomicAdd(&red[wr * 32 + mt * 16 + g], s1);
            atomicAdd(&red[wr * 32 + mt * 16 + g + 8], s2);
        }
    }
    __syncthreads();
    if (tid < 64) {
        int e = row0 + tid;
        float s = red[tid];
        float4 xd = *(const float4*)(g_xdiff + (size_t)e * 4);
        int d = s_dst[tid];
        atomicAdd(&g_xsum[d * 3 + 0], s * xd.x);
        atomicAdd(&g_xsum[d * 3 + 1], s * xd.y);
        atomicAdd(&g_xsum[d * 3 + 2], s * xd.z);
    }
}

// ---------------- node GEMM 1 (fp32) ----------------
__global__ __launch_bounds__(256, 2)
void k_n1(const float* __restrict__ nf, const float* __restrict__ W,
          const float* __restrict__ b) {
    __shared__ float As[TBK][128 + 4];
    __shared__ float Bs[TBK][128 + 4];
    const int tid = threadIdx.x;
    const int row0 = blockIdx.x * 128;
    const int col0 = blockIdx.y * 128;
    const int tx = tid & 15;
    const int ty = tid >> 4;
    u64 acc2[8][4];
#pragma unroll
    for (int i = 0; i < 8; i++)
#pragma unroll
        for (int j = 0; j < 4; j++) acc2[i][j] = 0ull;

    for (int kt = 0; kt < KN1 / TBK; kt++) {
#pragma unroll
        for (int i = 0; i < 2; i++) {
            int f = tid + i * 256;
            int r = f >> 2;
            int kk = (f & 3) << 2;
            int kg = kt * TBK + kk;
            int rr = min(row0 + r, NN - 1);
            float4 v;
            if (kg < INF)
                v = *(const float4*)(nf + (size_t)rr * INF + kg);
            else
                v = *(const float4*)(g_hneigh + (size_t)rr * HIDF + (kg - INF));
            As[kk + 0][r] = v.x; As[kk + 1][r] = v.y;
            As[kk + 2][r] = v.z; As[kk + 3][r] = v.w;
        }
#pragma unroll
        for (int i = 0; i < 2; i++) {
            int f = tid + i * 256;
            int kk = f >> 5;
            int c = (f & 31) << 2;
            *(float4*)&Bs[kk][c] =
                *(const float4*)(W + (size_t)(kt * TBK + kk) * HIDF + col0 + c);
        }
        __syncthreads();
#pragma unroll
        for (int k = 0; k < TBK; k++)
            mt_step(acc2, &As[k][0], &Bs[k][0], ty * 8, tx * 8);
        __syncthreads();
    }
    float bb[8];
#pragma unroll
    for (int j = 0; j < 8; j++) bb[j] = b[col0 + tx * 8 + j];
#pragma unroll
    for (int i = 0; i < 8; i++) {
        int row = row0 + ty * 8 + i;
        if (row < NN) {
            float a[8];
#pragma unroll
            for (int jp = 0; jp < 4; jp++) upk2(acc2[i][jp], a[2 * jp], a[2 * jp + 1]);
            float4 o0, o1;
            o0.x = silu_f(a[0] + bb[0]); o0.y = silu_f(a[1] + bb[1]);
            o0.z = silu_f(a[2] + bb[2]); o0.w = silu_f(a[3] + bb[3]);
            o1.x = silu_f(a[4] + bb[4]); o1.y = silu_f(a[5] + bb[5]);
            o1.z = silu_f(a[6] + bb[6]); o1.w = silu_f(a[7] + bb[7]);
            *(float4*)(g_hn1 + (size_t)row * HIDF + col0 + tx * 8) = o0;
            *(float4*)(g_hn1 + (size_t)row * HIDF + col0 + tx * 8 + 4) = o1;
        }
    }
}

// ---------------- node GEMM 2 + BN stats (fp32) ----------------
__global__ __launch_bounds__(256, 2)
void k_n2(const float* __restrict__ W, const float* __restrict__ b,
          float* __restrict__ out) {
    __shared__ float As[TBK][128 + 4];
    __shared__ float Bs[TBK][128 + 4];
    __shared__ float csum[128];
    __shared__ float csq[128];
    const int tid = threadIdx.x;
    const int row0 = blockIdx.x * 128;
    if (tid < 128) { csum[tid] = 0.0f; csq[tid] = 0.0f; }
    const int tx = tid & 15;
    const int ty = tid >> 4;
    u64 acc2[8][4];
#pragma unroll
    for (int i = 0; i < 8; i++)
#pragma unroll
        for (int j = 0; j < 4; j++) acc2[i][j] = 0ull;

    for (int kt = 0; kt < HIDF / TBK; kt++) {
#pragma unroll
        for (int i = 0; i < 2; i++) {
            int f = tid + i * 256;
            int r = f >> 2;
            int kk = (f & 3) << 2;
            int rr = min(row0 + r, NN - 1);
            float4 v = *(const float4*)(g_hn1 + (size_t)rr * HIDF + kt * TBK + kk);
            As[kk + 0][r] = v.x; As[kk + 1][r] = v.y;
            As[kk + 2][r] = v.z; As[kk + 3][r] = v.w;
        }
#pragma unroll
        for (int i = 0; i < 2; i++) {
            int f = tid + i * 256;
            int kk = f >> 5;
            int c = (f & 31) << 2;
            *(float4*)&Bs[kk][c] =
                *(const float4*)(W + (size_t)(kt * TBK + kk) * OUTF + c);
        }
        __syncthreads();
#pragma unroll
        for (int k = 0; k < TBK; k++)
            mt_step(acc2, &As[k][0], &Bs[k][0], ty * 8, tx * 8);
        __syncthreads();
    }
    float bb[8];
#pragma unroll
    for (int j = 0; j < 8; j++) bb[j] = b[tx * 8 + j];
    float cs[8], cq[8];
#pragma unroll
    for (int j = 0; j < 8; j++) { cs[j] = 0.0f; cq[j] = 0.0f; }
#pragma unroll
    for (int i = 0; i < 8; i++) {
        int row = row0 + ty * 8 + i;
        if (row < NN) {
            float a[8], h[8];
#pragma unroll
            for (int jp = 0; jp < 4; jp++) upk2(acc2[i][jp], a[2 * jp], a[2 * jp + 1]);
#pragma unroll
            for (int j = 0; j < 8; j++) {
                h[j] = a[j] + bb[j];
                cs[j] += h[j];
                cq[j] += h[j] * h[j];
            }
            *(float4*)(out + (size_t)row * OUTF + tx * 8) =
                make_float4(h[0], h[1], h[2], h[3]);
            *(float4*)(out + (size_t)row * OUTF + tx * 8 + 4) =
                make_float4(h[4], h[5], h[6], h[7]);
        }
    }
#pragma unroll
    for (int j = 0; j < 8; j++) {
        atomicAdd(&csum[tx * 8 + j], cs[j]);
        atomicAdd(&csq[tx * 8 + j], cq[j]);
    }
    __syncthreads();
    if (tid < 128) {
        atomicAdd(&g_colsum[tid], csum[tid]);
        atomicAdd(&g_colsq[tid], csq[tid]);
    }
}

// ---------------- x output ----------------
__global__ void k_xout(const float* __restrict__ coord, float* __restrict__ out) {
    int n = blockIdx.x * blockDim.x + threadIdx.x;
    if (n >= NN) return;
    float inv = 1.0f / fmaxf(g_deg[n], 1.0f);
    float* o = out + (size_t)NN * OUTF + n * 3;
    o[0] = coord[n * 3 + 0] + g_xsum[n * 3 + 0] * inv;
    o[1] = coord[n * 3 + 1] + g_xsum[n * 3 + 1] * inv;
    o[2] = coord[n * 3 + 2] + g_xsum[n * 3 + 2] * inv;
}

// ---------------- BatchNorm finalize ----------------
__global__ void k_bn(const float* __restrict__ gamma, const float* __restrict__ beta,
                     float* __restrict__ out) {
    int idx = blockIdx.x * blockDim.x + threadIdx.x;
    if (idx >= NN * OUTF) return;
    int c = idx & (OUTF - 1);
    const float invN = 1.0f / (float)NN;
    float mu = g_colsum[c] * invN;
    float var = g_colsq[c] * invN - mu * mu;
    float h = out[idx];
    out[idx] = (h - mu) * rsqrtf(var + 1e-5f) * gamma[c] + beta[c];
}

// ---------------- launch ----------------
extern "C" void kernel_launch(void* const* d_in, const int* in_sizes, int n_in,
                              void* d_out, int out_size) {
    const float* nf    = (const float*)d_in[0];
    const float* coord = (const float*)d_in[1];
    const int*   src   = (const int*)d_in[2];
    const int*   dst   = (const int*)d_in[3];
    const float* We1   = (const float*)d_in[4];
    const float* be1   = (const float*)d_in[5];
    const float* We2   = (const float*)d_in[6];
    const float* be2   = (const float*)d_in[7];
    const float* Wc1   = (const float*)d_in[8];
    const float* bc1   = (const float*)d_in[9];
    const float* Wc2   = (const float*)d_in[10];
    const float* Wn1   = (const float*)d_in[11];
    const float* bn1   = (const float*)d_in[12];
    const float* Wn2   = (const float*)d_in[13];
    const float* bn2   = (const float*)d_in[14];
    const float* gamma = (const float*)d_in[15];
    const float* beta  = (const float*)d_in[16];
    float* out = (float*)d_out;

    void* p;
    cudaGetSymbolAddress(&p, g_hneigh);
    cudaMemsetAsync(p, 0, sizeof(float) * (size_t)NN * HIDF);
    cudaGetSymbolAddress(&p, g_xsum);
    cudaMemsetAsync(p, 0, sizeof(float) * NN * 3);
    cudaGetSymbolAddress(&p, g_deg);
    cudaMemsetAsync(p, 0, sizeof(float) * NN);
    cudaGetSymbolAddress(&p, g_colsum);
    cudaMemsetAsync(p, 0, sizeof(float) * OUTF);
    cudaGetSymbolAddress(&p, g_colsq);
    cudaMemsetAsync(p, 0, sizeof(float) * OUTF);

    k_cvtw<<<(HIDF * HIDF + 255) / 256, 256>>>(We2, Wc1);
    k_geom<<<(NE + 255) / 256, 256>>>(coord, src, dst);

    dim3 gp((NN + 127) / 128, HIDF / 128, 2);
    k_pre<<<gp, 256>>>(nf, We1);

    k_e2<<<NE / 64, 512>>>(src, dst, We1 + (size_t)2 * INF * HIDF, be1, be2);
    k_c<<<NE / 64, 512>>>(dst, bc1, Wc2);

    dim3 gn((NN + 127) / 128, HIDF / 128);
    k_n1<<<gn, 256>>>(nf, Wn1, bn1);
    k_n2<<<(NN + 127) / 128, 256>>>(Wn2, bn2, out);

    k_xout<<<(NN + 255) / 256, 256>>>(coord, out);
    k_bn<<<(NN * OUTF + 255) / 256, 256>>>(gamma, beta, out);
}